// round 1
// baseline (speedup 1.0000x reference)
#include <cuda_runtime.h>

// CGBlock: per-slice MLP (Linear -> BN -> ReLU -> Linear -> BN -> ReLU -> Linear),
// context gate by c_mlp(c), max-pool over sequence.
// B=256, S=512, D=128, fp32.
//
// Kernel 1 (mlp_kernel, grid 513): bid 0 computes c_out; bids 1..512 compute slice
//   i = bid-1 of s entirely in SMEM (3 fused GEMM+BN+ReLU layers), then gate with
//   c_out (flag spin; c CTA is in wave 1 so the wait is ~0) and write s_out.
// Kernel 2 (maxpool_kernel): max over S, writes aggregated_c, resets the flag
//   so the captured graph replays deterministically.

#define AP 132            // act row pitch (floats), 16B-aligned, conflict-benign
#define WP 130            // transposed-weight row pitch (floats), 8B-aligned
#define THREADS 512
#define SM_ACT_F (256 * AP)
#define SM_WT_F  (128 * WP)
#define SM_TOTAL_F (SM_ACT_F + SM_WT_F + 4 * 128)
#define SM_BYTES (SM_TOTAL_F * 4)

__device__ float g_c_out[256 * 128];
__device__ int g_flag = 0;

typedef unsigned long long u64;

__device__ __forceinline__ u64 pack2(float x) {
    u64 r;
    unsigned int xi = __float_as_uint(x);
    asm("mov.b64 %0, {%1, %1};" : "=l"(r) : "r"(xi));
    return r;
}
__device__ __forceinline__ void fma2(u64& d, u64 a, u64 b) {
    asm("fma.rn.f32x2 %0, %1, %2, %0;" : "+l"(d) : "l"(a), "l"(b));
}
__device__ __forceinline__ void unpack2(u64 v, float& lo, float& hi) {
    unsigned int a, b;
    asm("mov.b64 {%0, %1}, %2;" : "=r"(a), "=r"(b) : "l"(v));
    lo = __uint_as_float(a);
    hi = __uint_as_float(b);
}

// Load W[j][k] (row-major 128x128) transposed into smem wt[k][j] (pitch WP).
__device__ __forceinline__ void load_wt(float* sm_wt, const float* __restrict__ w, int tid) {
    for (int idx = tid; idx < 128 * 32; idx += THREADS) {
        int j = idx >> 5;
        int kc = (idx & 31) << 2;
        float4 v = *(const float4*)(w + j * 128 + kc);
        sm_wt[(kc + 0) * WP + j] = v.x;
        sm_wt[(kc + 1) * WP + j] = v.y;
        sm_wt[(kc + 2) * WP + j] = v.z;
        sm_wt[(kc + 3) * WP + j] = v.w;
    }
}

// Y[256][128] = act[256][128] @ W^T, register-tiled 8 rows x 8 cols (4 f32x2 pairs)
// per thread, FFMA2 (packed f32x2) for 2x fp32 pipe rate on sm_103a.
__device__ __forceinline__ void gemm(u64 (&acc)[8][4], const float* sm_act,
                                     const float* sm_wt, int m, int g) {
#pragma unroll
    for (int i = 0; i < 8; ++i)
#pragma unroll
        for (int p = 0; p < 4; ++p) acc[i][p] = 0ULL;

    const float* a0 = sm_act + (g * 8) * AP;
#pragma unroll 2
    for (int k = 0; k < 128; ++k) {
        const float* wk = sm_wt + k * WP + 2 * m;
        u64 b0 = *(const u64*)(wk);
        u64 b1 = *(const u64*)(wk + 32);
        u64 b2 = *(const u64*)(wk + 64);
        u64 b3 = *(const u64*)(wk + 96);
#pragma unroll
        for (int i = 0; i < 8; ++i) {
            u64 a2 = pack2(a0[i * AP + k]);
            fma2(acc[i][0], a2, b0);
            fma2(acc[i][1], a2, b1);
            fma2(acc[i][2], a2, b2);
            fma2(acc[i][3], a2, b3);
        }
    }
}

// BN (training-mode, biased var, over the 256 rows) + ReLU; writes normalized
// activations back into sm_act. Scratch aliases the weight tile region.
__device__ __forceinline__ void bn_relu(u64 (&acc)[8][4], float* sm_act, float* sm_scr,
                                        float* sm_sc, float* sm_sh,
                                        const float* sm_gm, const float* sm_bt,
                                        int m, int g, int tid) {
    float* ssum = sm_scr;             // [32][128]
    float* ssq  = sm_scr + 32 * 128;  // [32][128]
    __syncthreads();  // all GEMM reads of act/wt complete

#pragma unroll
    for (int p = 0; p < 4; ++p) {
        int j0 = 2 * m + 32 * p;
        float s0 = 0.f, q0 = 0.f, s1 = 0.f, q1 = 0.f;
#pragma unroll
        for (int i = 0; i < 8; ++i) {
            float lo, hi;
            unpack2(acc[i][p], lo, hi);
            s0 += lo; q0 += lo * lo;
            s1 += hi; q1 += hi * hi;
        }
        ssum[g * 128 + j0] = s0;     ssq[g * 128 + j0] = q0;
        ssum[g * 128 + j0 + 1] = s1; ssq[g * 128 + j0 + 1] = q1;
    }
    __syncthreads();

    if (tid < 128) {
        float s = 0.f, q = 0.f;
#pragma unroll
        for (int gg = 0; gg < 32; ++gg) {
            s += ssum[gg * 128 + tid];
            q += ssq[gg * 128 + tid];
        }
        float mean = s * (1.0f / 256.0f);
        float var  = q * (1.0f / 256.0f) - mean * mean;
        float inv  = rsqrtf(var + 1e-5f);
        float sc   = sm_gm[tid] * inv;
        sm_sc[tid] = sc;
        sm_sh[tid] = sm_bt[tid] - mean * sc;  // note: linear bias b cancels in BN
    }
    __syncthreads();

#pragma unroll
    for (int p = 0; p < 4; ++p) {
        int j0 = 2 * m + 32 * p;
        float sc0 = sm_sc[j0], sh0 = sm_sh[j0];
        float sc1 = sm_sc[j0 + 1], sh1 = sm_sh[j0 + 1];
#pragma unroll
        for (int i = 0; i < 8; ++i) {
            float lo, hi;
            unpack2(acc[i][p], lo, hi);
            float2 v;
            v.x = fmaxf(fmaf(lo, sc0, sh0), 0.0f);
            v.y = fmaxf(fmaf(hi, sc1, sh1), 0.0f);
            *(float2*)(sm_act + (g * 8 + i) * AP + j0) = v;
        }
    }
}

__global__ __launch_bounds__(THREADS, 1)
void mlp_kernel(const float* __restrict__ s, const float* __restrict__ c,
                const float* __restrict__ sw1, const float* __restrict__ sg1,
                const float* __restrict__ sbe1,
                const float* __restrict__ sw2, const float* __restrict__ sg2,
                const float* __restrict__ sbe2,
                const float* __restrict__ sw3, const float* __restrict__ sb3,
                const float* __restrict__ cw1, const float* __restrict__ cg1,
                const float* __restrict__ cbe1,
                const float* __restrict__ cw2, const float* __restrict__ cg2,
                const float* __restrict__ cbe2,
                const float* __restrict__ cw3, const float* __restrict__ cb3,
                float* __restrict__ out) {
    extern __shared__ float sm[];
    float* sm_act = sm;
    float* sm_wt  = sm + SM_ACT_F;
    float* sm_sc  = sm_wt + SM_WT_F;
    float* sm_sh  = sm_sc + 128;
    float* sm_gm  = sm_sh + 128;
    float* sm_bt  = sm_gm + 128;

    const int tid = threadIdx.x;
    const int m = tid & 15;   // column group
    const int g = tid >> 4;   // row group
    const bool is_c = (blockIdx.x == 0);
    const int slice = (int)blockIdx.x - 1;

    const float* w1  = is_c ? cw1 : sw1;
    const float* w2  = is_c ? cw2 : sw2;
    const float* w3  = is_c ? cw3 : sw3;
    const float* g1  = is_c ? cg1 : sg1;
    const float* g2  = is_c ? cg2 : sg2;
    const float* be1 = is_c ? cbe1 : sbe1;
    const float* be2 = is_c ? cbe2 : sbe2;
    const float* b3  = is_c ? cb3 : sb3;

    // Stage input [256,128] into SMEM (vectorized, coalesced).
    {
        const float* src = is_c ? c : (s + (size_t)slice * 128);
        const size_t rstride = is_c ? (size_t)128 : (size_t)512 * 128;
        for (int idx = tid; idx < 256 * 32; idx += THREADS) {
            int r = idx >> 5;
            int kc = (idx & 31) << 2;
            float4 v = *(const float4*)(src + (size_t)r * rstride + kc);
            *(float4*)(sm_act + r * AP + kc) = v;
        }
    }
    load_wt(sm_wt, w1, tid);
    if (tid < 128) { sm_gm[tid] = g1[tid]; sm_bt[tid] = be1[tid]; }
    __syncthreads();

    u64 acc[8][4];

    // Layer 1
    gemm(acc, sm_act, sm_wt, m, g);
    bn_relu(acc, sm_act, sm_wt, sm_sc, sm_sh, sm_gm, sm_bt, m, g, tid);
    load_wt(sm_wt, w2, tid);
    if (tid < 128) { sm_gm[tid] = g2[tid]; sm_bt[tid] = be2[tid]; }
    __syncthreads();

    // Layer 2
    gemm(acc, sm_act, sm_wt, m, g);
    bn_relu(acc, sm_act, sm_wt, sm_sc, sm_sh, sm_gm, sm_bt, m, g, tid);
    load_wt(sm_wt, w3, tid);
    if (tid < 128) sm_bt[tid] = b3[tid];
    __syncthreads();

    // Layer 3 (linear + bias, no BN)
    gemm(acc, sm_act, sm_wt, m, g);

    if (is_c) {
#pragma unroll
        for (int p = 0; p < 4; ++p) {
            int j0 = 2 * m + 32 * p;
            float bb0 = sm_bt[j0], bb1 = sm_bt[j0 + 1];
#pragma unroll
            for (int i = 0; i < 8; ++i) {
                float lo, hi;
                unpack2(acc[i][p], lo, hi);
                float2 v; v.x = lo + bb0; v.y = hi + bb1;
                *(float2*)&g_c_out[(g * 8 + i) * 128 + j0] = v;
            }
        }
        __threadfence();
        __syncthreads();
        if (tid == 0) atomicExch(&g_flag, 1);
    } else {
        // Wait for c_out (c CTA is bid 0, resident in wave 1 -> no deadlock,
        // and it finishes at the same time as other wave-1 CTAs -> ~0 wait).
        if (tid == 0) {
            while (atomicAdd(&g_flag, 0) == 0) { }
            __threadfence();
        }
        __syncthreads();
#pragma unroll
        for (int p = 0; p < 4; ++p) {
            int j0 = 2 * m + 32 * p;
            float bb0 = sm_bt[j0], bb1 = sm_bt[j0 + 1];
#pragma unroll
            for (int i = 0; i < 8; ++i) {
                int r = g * 8 + i;
                float lo, hi;
                unpack2(acc[i][p], lo, hi);
                float2 cv = __ldcg((const float2*)&g_c_out[r * 128 + j0]);
                float2 v;
                v.x = (lo + bb0) * cv.x;
                v.y = (hi + bb1) * cv.y;
                *(float2*)(out + ((size_t)r * 512 + slice) * 128 + j0) = v;
            }
        }
    }
}

__global__ void maxpool_kernel(const float* __restrict__ so, float* __restrict__ agg) {
    if (blockIdx.x == 0 && threadIdx.x == 0) g_flag = 0;  // reset for next graph replay
    int idx = blockIdx.x * blockDim.x + threadIdx.x;      // 0..32767 = b*128 + d
    int b = idx >> 7;
    int d = idx & 127;
    const float* p = so + (size_t)b * 512 * 128 + d;
    float mx = -3.402823466e38f;
#pragma unroll 8
    for (int i = 0; i < 512; ++i) mx = fmaxf(mx, p[(size_t)i * 128]);
    agg[idx] = mx;
}

extern "C" void kernel_launch(void* const* d_in, const int* in_sizes, int n_in,
                              void* d_out, int out_size) {
    const float* s    = (const float*)d_in[0];
    const float* c    = (const float*)d_in[1];
    const float* sw1  = (const float*)d_in[2];
    // d_in[3] = s_b1: bias cancels in BN, unused
    const float* sg1  = (const float*)d_in[4];
    const float* sbe1 = (const float*)d_in[5];
    const float* sw2  = (const float*)d_in[6];
    // d_in[7] = s_b2 unused
    const float* sg2  = (const float*)d_in[8];
    const float* sbe2 = (const float*)d_in[9];
    const float* sw3  = (const float*)d_in[10];
    const float* sb3  = (const float*)d_in[11];
    const float* cw1  = (const float*)d_in[12];
    // d_in[13] = c_b1 unused
    const float* cg1  = (const float*)d_in[14];
    const float* cbe1 = (const float*)d_in[15];
    const float* cw2  = (const float*)d_in[16];
    // d_in[17] = c_b2 unused
    const float* cg2  = (const float*)d_in[18];
    const float* cbe2 = (const float*)d_in[19];
    const float* cw3  = (const float*)d_in[20];
    const float* cb3  = (const float*)d_in[21];
    float* out = (float*)d_out;

    cudaFuncSetAttribute(mlp_kernel, cudaFuncAttributeMaxDynamicSharedMemorySize, SM_BYTES);

    mlp_kernel<<<513, THREADS, SM_BYTES>>>(s, c,
                                           sw1, sg1, sbe1, sw2, sg2, sbe2, sw3, sb3,
                                           cw1, cg1, cbe1, cw2, cg2, cbe2, cw3, cb3,
                                           out);

    float* agg = out + ((size_t)out_size - 256 * 128);
    maxpool_kernel<<<128, 256>>>(out, agg);
}

// round 3
// speedup vs baseline: 3.0110x; 3.0110x over previous
#include <cuda_runtime.h>
#include <cuda_bf16.h>
#include <cstdint>

// CGBlock: per-slice 3-layer MLP (Linear->BN->ReLU x2 ->Linear), context gate,
// max-pool. B=256, S=512, D=128 fp32.
//
// One kernel, two arch bodies:
//  - sm_103a/sm_100a SASS pass: tcgen05 bf16x3-split GEMMs (D = AhBh + AhBl + AlBh,
//    fp32 TMEM accum), whole layer chain in SMEM/TMEM.
//  - any other pass (e.g. the harness's compute_103 PTX pass, where tcgen05 is
//    illegal): proven FFMA2 (f32x2) SIMT path.
// Grid 513: bid 0 = c-path (g_c_out + flag), bids 1..512 = s slices.

#define THREADS 512

#if defined(__CUDA_ARCH__) && (defined(__CUDA_ARCH_FEAT_SM103_ALL) || defined(__CUDA_ARCH_FEAT_SM100_ALL) || defined(__CUDA_ARCH_FEAT_SM101_ALL))
#define USE_TC 1
#else
#define USE_TC 0
#endif

// ---------------- shared state ----------------
__device__ float4 g_c_out[256 * 32];
__device__ int g_flag = 0;
__device__ float g_part[256 * 8 * 128];

// ---------------- TC-path SMEM layout (bytes) ----------------
#define OFF_TMEM 0
#define OFF_MBAR 8
#define OFF_AHI  1024                 // A_hi: 2 tiles x 32768 (128r x 128k bf16, SW128 blocked)
#define OFF_ALO  (1024 + 65536)       // A_lo
#define OFF_SCR  1024                 // fp32 Y scratch [256][128], aliases A (time-separated)
#define OFF_WHI  132096               // W_hi 32768
#define OFF_WLO  164864               // W_lo 32768
#define OFF_SC   197632               // BN scale [128]
#define OFF_SH   198144               // BN shift [128]
#define OFF_PST  198656               // partial stats f32[1024] (512 sum + 512 sumsq)
#define SM_TC_BYTES 202752

// ---------------- fallback SMEM layout (floats) ----------------
#define AP 132
#define WP 130
#define SM_ACT_F (256 * AP)
#define SM_WT_F  (128 * WP)
#define SM_FB_BYTES ((SM_ACT_F + SM_WT_F + 4 * 128) * 4)

#define SM_BYTES_MAX (SM_FB_BYTES > SM_TC_BYTES ? SM_FB_BYTES : SM_TC_BYTES)

// idesc kind::f16: c=F32, a=BF16, b=BF16, N=128, M=128
#define IDESC 0x08200490u

// ======================= common helpers =======================
typedef unsigned long long u64;

__device__ __forceinline__ uint32_t smem_u32(const void* p) {
    uint32_t a;
    asm("{ .reg .u64 t; cvta.to.shared.u64 t, %1; cvt.u32.u64 %0, t; }" : "=r"(a) : "l"(p));
    return a;
}

#if USE_TC
// ---------------- tcgen05 PTX (compiled only on arch-specific passes) ----------------
__device__ __forceinline__ uint32_t elect_one_pred() {
    uint32_t pred;
    asm volatile("{\n\t.reg .pred p;\n\telect.sync _|p, 0xFFFFFFFF;\n\tselp.b32 %0, 1, 0, p;\n\t}"
                 : "=r"(pred));
    return pred;
}
#define TCGEN05_ALLOC(a, n) \
    asm volatile("tcgen05.alloc.cta_group::1.sync.aligned.shared::cta.b32 [%0], %1;" \
                 :: "r"((uint32_t)(a)), "r"((uint32_t)(n)) : "memory")
#define TCGEN05_DEALLOC(t, n) \
    asm volatile("tcgen05.dealloc.cta_group::1.sync.aligned.b32 %0, %1;" :: "r"(t), "r"((uint32_t)(n)))
#define TCGEN05_RELINQ() \
    asm volatile("tcgen05.relinquish_alloc_permit.cta_group::1.sync.aligned;")
#define TCGEN05_COMMIT(m) \
    asm volatile("tcgen05.commit.cta_group::1.mbarrier::arrive::one.shared::cluster.b64 [%0];" \
                 :: "r"((uint32_t)(m)) : "memory")
#define TCGEN05_WAIT_LD()  asm volatile("tcgen05.wait::ld.sync.aligned;" ::: "memory")
#define TCGEN05_FENCE_BEFORE() asm volatile("tcgen05.fence::before_thread_sync;" ::: "memory")
#define TCGEN05_FENCE_AFTER()  asm volatile("tcgen05.fence::after_thread_sync;" ::: "memory")
#define FENCE_PROXY() asm volatile("fence.proxy.async.shared::cta;" ::: "memory")
#define MBARRIER_INIT(m, c) \
    asm volatile("mbarrier.init.shared.b64 [%0], %1;" :: "r"((uint32_t)(m)), "r"((uint32_t)(c)) : "memory")
#define MBARRIER_INVAL(m) \
    asm volatile("mbarrier.inval.shared.b64 [%0];" :: "r"((uint32_t)(m)) : "memory")
#define MBARRIER_WAIT_PARITY(mb, ph) do { \
    uint32_t _m = (uint32_t)(mb); uint32_t _p = (uint32_t)(ph); uint32_t _d; \
    asm volatile("{\n\t.reg .pred p;\n\t" \
        "mbarrier.try_wait.parity.acquire.cta.shared::cta.b64 p, [%1], %2;\n\t" \
        "selp.b32 %0, 1, 0, p;\n\t}" : "=r"(_d) : "r"(_m), "r"(_p) : "memory"); \
    if (!_d) { \
        asm volatile("{\n\t.reg .pred P1;\n\t" \
            "WAIT_LOOP_%=:\n\t" \
            "mbarrier.try_wait.parity.acquire.cta.shared::cta.b64 P1, [%0], %1, 0x989680;\n\t" \
            "@P1 bra.uni WAIT_DONE_%=;\n\t" \
            "bra.uni WAIT_LOOP_%=;\n\t" \
            "WAIT_DONE_%=:\n\t}" :: "r"(_m), "r"(_p) : "memory"); \
    } \
} while (0)
#define TCGEN05_LD_X32(r, a) \
    asm volatile("tcgen05.ld.sync.aligned.32x32b.x32.b32 " \
        "{%0, %1, %2, %3, %4, %5, %6, %7, %8, %9, %10, %11, %12, %13, %14, %15, " \
        " %16, %17, %18, %19, %20, %21, %22, %23, %24, %25, %26, %27, %28, %29, %30, %31}, [%32];" \
        : "=r"((r)[0]),  "=r"((r)[1]),  "=r"((r)[2]),  "=r"((r)[3]), \
          "=r"((r)[4]),  "=r"((r)[5]),  "=r"((r)[6]),  "=r"((r)[7]), \
          "=r"((r)[8]),  "=r"((r)[9]),  "=r"((r)[10]), "=r"((r)[11]), \
          "=r"((r)[12]), "=r"((r)[13]), "=r"((r)[14]), "=r"((r)[15]), \
          "=r"((r)[16]), "=r"((r)[17]), "=r"((r)[18]), "=r"((r)[19]), \
          "=r"((r)[20]), "=r"((r)[21]), "=r"((r)[22]), "=r"((r)[23]), \
          "=r"((r)[24]), "=r"((r)[25]), "=r"((r)[26]), "=r"((r)[27]), \
          "=r"((r)[28]), "=r"((r)[29]), "=r"((r)[30]), "=r"((r)[31]) \
        : "r"(a))

__device__ __forceinline__ void mma_bf16_ss(uint32_t d, uint64_t a, uint64_t b, uint32_t en) {
    asm volatile(
        "{\n\t.reg .pred p;\n\tsetp.ne.u32 p, %5, 0;\n\t"
        "tcgen05.mma.cta_group::1.kind::f16 [%0], %1, %2, %3, {%4, %4, %4, %4}, p;\n\t}"
        :: "r"(d), "l"(a), "l"(b), "r"(IDESC), "r"(0u), "r"(en) : "memory");
}
__device__ __forceinline__ uint64_t make_desc(uint32_t addr) {
    const uint64_t base = (uint64_t(2) << 61) | (uint64_t(1) << 46) |
                          (uint64_t(64) << 32) | (uint64_t(1) << 16);
    return base | ((uint64_t)(addr >> 4) & 0x3FFF);
}
// Blocked SW128 addr for bf16 tile: atoms 8r x 64 bf16, 16 atom-rows x 2 atom-cols.
__device__ __forceinline__ uint32_t swb(int rl, int j0) {
    uint32_t off = (uint32_t)((((rl >> 3) + ((j0 >> 6) << 4)) << 10) + ((rl & 7) << 7) + ((j0 & 63) << 1));
    return off ^ ((off >> 3) & 0x70);
}
__device__ __forceinline__ void split8(const float* f, uint4& h, uint4& l) {
    uint32_t hh[4], ll[4];
#pragma unroll
    for (int i = 0; i < 4; ++i) {
        float x = f[2 * i], y = f[2 * i + 1];
        __nv_bfloat162 hb = __floats2bfloat162_rn(x, y);
        hh[i] = *(uint32_t*)&hb;
        float lx = x - __bfloat162float(hb.x);
        float ly = y - __bfloat162float(hb.y);
        __nv_bfloat162 lb = __floats2bfloat162_rn(lx, ly);
        ll[i] = *(uint32_t*)&lb;
    }
    h = make_uint4(hh[0], hh[1], hh[2], hh[3]);
    l = make_uint4(ll[0], ll[1], ll[2], ll[3]);
}
__device__ __forceinline__ void load_split_gmem(char* sm, uint32_t hiBase, uint32_t loBase,
                                                const float* __restrict__ src, int nrows,
                                                size_t rstride, int tid) {
    int items = nrows * 16;
    for (int idx = tid; idx < items; idx += THREADS) {
        int row = idx >> 4;
        int ch = idx & 15;
        const float* p = src + (size_t)row * rstride + ch * 8;
        float4 a = *(const float4*)p;
        float4 b = *(const float4*)(p + 4);
        float f[8] = {a.x, a.y, a.z, a.w, b.x, b.y, b.z, b.w};
        uint4 H, L;
        split8(f, H, L);
        int tile = row >> 7;
        uint32_t off = swb(row & 127, ch * 8) + tile * 32768;
        *(uint4*)(sm + hiBase + off) = H;
        *(uint4*)(sm + loBase + off) = L;
    }
}
#endif  // USE_TC

// ---------------- fallback (FFMA2) helpers: compiled everywhere ----------------
__device__ __forceinline__ u64 pack2(float x) {
    u64 r;
    unsigned int xi = __float_as_uint(x);
    asm("mov.b64 %0, {%1, %1};" : "=l"(r) : "r"(xi));
    return r;
}
__device__ __forceinline__ void fma2(u64& d, u64 a, u64 b) {
    asm("fma.rn.f32x2 %0, %1, %2, %0;" : "+l"(d) : "l"(a), "l"(b));
}
__device__ __forceinline__ void unpack2(u64 v, float& lo, float& hi) {
    unsigned int a, b;
    asm("mov.b64 {%0, %1}, %2;" : "=r"(a), "=r"(b) : "l"(v));
    lo = __uint_as_float(a);
    hi = __uint_as_float(b);
}
__device__ __forceinline__ void load_wt(float* sm_wt, const float* __restrict__ w, int tid) {
    for (int idx = tid; idx < 128 * 32; idx += THREADS) {
        int j = idx >> 5;
        int kc = (idx & 31) << 2;
        float4 v = *(const float4*)(w + j * 128 + kc);
        sm_wt[(kc + 0) * WP + j] = v.x;
        sm_wt[(kc + 1) * WP + j] = v.y;
        sm_wt[(kc + 2) * WP + j] = v.z;
        sm_wt[(kc + 3) * WP + j] = v.w;
    }
}
__device__ __forceinline__ void fb_gemm(u64 (&acc)[8][4], const float* sm_act,
                                        const float* sm_wt, int m, int g) {
#pragma unroll
    for (int i = 0; i < 8; ++i)
#pragma unroll
        for (int p = 0; p < 4; ++p) acc[i][p] = 0ULL;
    const float* a0 = sm_act + (g * 8) * AP;
#pragma unroll 2
    for (int k = 0; k < 128; ++k) {
        const float* wk = sm_wt + k * WP + 2 * m;
        u64 b0 = *(const u64*)(wk);
        u64 b1 = *(const u64*)(wk + 32);
        u64 b2 = *(const u64*)(wk + 64);
        u64 b3 = *(const u64*)(wk + 96);
#pragma unroll
        for (int i = 0; i < 8; ++i) {
            u64 a2 = pack2(a0[i * AP + k]);
            fma2(acc[i][0], a2, b0);
            fma2(acc[i][1], a2, b1);
            fma2(acc[i][2], a2, b2);
            fma2(acc[i][3], a2, b3);
        }
    }
}
__device__ __forceinline__ void fb_bn_relu(u64 (&acc)[8][4], float* sm_act, float* sm_scr,
                                           float* sm_sc, float* sm_sh,
                                           const float* sm_gm, const float* sm_bt,
                                           int m, int g, int tid) {
    float* ssum = sm_scr;
    float* ssq  = sm_scr + 32 * 128;
    __syncthreads();
#pragma unroll
    for (int p = 0; p < 4; ++p) {
        int j0 = 2 * m + 32 * p;
        float s0 = 0.f, q0 = 0.f, s1 = 0.f, q1 = 0.f;
#pragma unroll
        for (int i = 0; i < 8; ++i) {
            float lo, hi;
            unpack2(acc[i][p], lo, hi);
            s0 += lo; q0 += lo * lo;
            s1 += hi; q1 += hi * hi;
        }
        ssum[g * 128 + j0] = s0;     ssq[g * 128 + j0] = q0;
        ssum[g * 128 + j0 + 1] = s1; ssq[g * 128 + j0 + 1] = q1;
    }
    __syncthreads();
    if (tid < 128) {
        float s = 0.f, q = 0.f;
#pragma unroll
        for (int gg = 0; gg < 32; ++gg) {
            s += ssum[gg * 128 + tid];
            q += ssq[gg * 128 + tid];
        }
        float mean = s * (1.0f / 256.0f);
        float var  = q * (1.0f / 256.0f) - mean * mean;
        float inv  = rsqrtf(var + 1e-5f);
        float sc   = sm_gm[tid] * inv;
        sm_sc[tid] = sc;
        sm_sh[tid] = sm_bt[tid] - mean * sc;
    }
    __syncthreads();
#pragma unroll
    for (int p = 0; p < 4; ++p) {
        int j0 = 2 * m + 32 * p;
        float sc0 = sm_sc[j0], sh0 = sm_sh[j0];
        float sc1 = sm_sc[j0 + 1], sh1 = sm_sh[j0 + 1];
#pragma unroll
        for (int i = 0; i < 8; ++i) {
            float lo, hi;
            unpack2(acc[i][p], lo, hi);
            float2 v;
            v.x = fmaxf(fmaf(lo, sc0, sh0), 0.0f);
            v.y = fmaxf(fmaf(hi, sc1, sh1), 0.0f);
            *(float2*)(sm_act + (g * 8 + i) * AP + j0) = v;
        }
    }
}

// ============================= the MLP kernel =============================
__global__ void __launch_bounds__(THREADS, 1)
mlp_kernel(const float* __restrict__ s, const float* __restrict__ c,
           const float* __restrict__ sw1, const float* __restrict__ sg1, const float* __restrict__ sbe1,
           const float* __restrict__ sw2, const float* __restrict__ sg2, const float* __restrict__ sbe2,
           const float* __restrict__ sw3, const float* __restrict__ sb3,
           const float* __restrict__ cw1, const float* __restrict__ cg1, const float* __restrict__ cbe1,
           const float* __restrict__ cw2, const float* __restrict__ cg2, const float* __restrict__ cbe2,
           const float* __restrict__ cw3, const float* __restrict__ cb3,
           float* __restrict__ out) {
    extern __shared__ char smc[];
    const int tid = threadIdx.x;
    const bool is_c = (blockIdx.x == 0);
    const int slice = (int)blockIdx.x - 1;

    const float *W1, *W2, *W3, *G1, *G2, *B1, *B2, *B3;
    if (is_c) { W1=cw1; W2=cw2; W3=cw3; G1=cg1; G2=cg2; B1=cbe1; B2=cbe2; B3=cb3; }
    else      { W1=sw1; W2=sw2; W3=sw3; G1=sg1; G2=sg2; B1=sbe1; B2=sbe2; B3=sb3; }

#if USE_TC
    // ======================= tcgen05 path =======================
    char* sm = smc;
    const uint32_t smb = smem_u32(sm);
    const int wid = tid >> 5;
    const int lane = tid & 31;
    const float* W[3] = {W1, W2, W3};
    const float* GM[2] = {G1, G2};
    const float* BT[2] = {B1, B2};

    if (wid == 0) {
        TCGEN05_ALLOC(smb + OFF_TMEM, 256);
        TCGEN05_RELINQ();
    }
    if (tid == 0) MBARRIER_INIT(smb + OFF_MBAR, 1);
    __syncthreads();
    uint32_t tmem;
    asm volatile("ld.shared.b32 %0, [%1];" : "=r"(tmem) : "r"(smb + OFF_TMEM));

    {
        const float* src = is_c ? c : (s + (size_t)slice * 128);
        size_t rstride = is_c ? (size_t)128 : (size_t)512 * 128;
        load_split_gmem(sm, OFF_AHI, OFF_ALO, src, 256, rstride, tid);
    }
    load_split_gmem(sm, OFF_WHI, OFF_WLO, W[0], 128, 128, tid);
    FENCE_PROXY();
    __syncthreads();

    // 16 warps: tile = (wid>>2)&1 (TMEM col block), colhalf = wid>>3 (64-col half),
    // subpartition rows = (wid&3)*32 + lane.
    const int tile = (wid >> 2) & 1;
    const int colhalf = wid >> 3;
    const int myrow = tile * 128 + ((wid & 3) << 5) + lane;
    const int rl = myrow & 127;
    const int jbase = colhalf * 64;

    float* scrf = (float*)(sm + OFF_SCR);
    float* scv = (float*)(sm + OFF_SC);
    float* shv = (float*)(sm + OFF_SH);
    float* pst = (float*)(sm + OFF_PST);

    uint32_t d[64];

#pragma unroll 1
    for (int layer = 0; layer < 3; ++layer) {
        if (wid == 0) {
            if (elect_one_pred()) {
                uint64_t bh = make_desc(smb + OFF_WHI);
                uint64_t bl = make_desc(smb + OFF_WLO);
#pragma unroll
                for (int T = 0; T < 2; ++T) {
                    uint64_t ah = make_desc(smb + OFF_AHI + T * 32768);
                    uint64_t al = make_desc(smb + OFF_ALO + T * 32768);
#pragma unroll
                    for (int pass = 0; pass < 3; ++pass) {
                        uint64_t ad = (pass == 2) ? al : ah;
                        uint64_t bd = (pass == 1) ? bl : bh;
#pragma unroll
                        for (int ks = 0; ks < 8; ++ks) {
                            uint32_t off = ((ks >> 2) << 10) + ((ks & 3) << 1);
                            mma_bf16_ss(tmem + T * 128, ad + off, bd + off,
                                        (pass | ks) ? 1u : 0u);
                        }
                    }
                }
                TCGEN05_COMMIT(smb + OFF_MBAR);
            }
        }
        MBARRIER_WAIT_PARITY(smb + OFF_MBAR, layer & 1);
        TCGEN05_FENCE_AFTER();

        {
            uint32_t tb = tmem + tile * 128 + jbase;
            TCGEN05_LD_X32(d + 0, tb + 0);
            TCGEN05_LD_X32(d + 32, tb + 32);
            TCGEN05_WAIT_LD();
        }
        TCGEN05_FENCE_BEFORE();

        if (layer < 2) {
            load_split_gmem(sm, OFF_WHI, OFF_WLO, W[layer + 1], 128, 128, tid);

            float4* mr = (float4*)(scrf + (size_t)myrow * 128 + jbase);
#pragma unroll
            for (int q = 0; q < 16; ++q) {
                float4 v;
                v.x = __uint_as_float(d[4 * q + 0]);
                v.y = __uint_as_float(d[4 * q + 1]);
                v.z = __uint_as_float(d[4 * q + 2]);
                v.w = __uint_as_float(d[4 * q + 3]);
                mr[q] = v;
            }
            __syncthreads();

            // BN stats: 512 threads, (col, row-quarter) partials -> 128 combine
            {
                int colq = tid & 127;
                int qr = tid >> 7;
                const float* bp = scrf + (size_t)qr * 64 * 128 + colq;
                float ss = 0.f, qq = 0.f;
#pragma unroll 8
                for (int r = 0; r < 64; ++r) {
                    float v = bp[(size_t)r * 128];
                    ss += v;
                    qq = fmaf(v, v, qq);
                }
                pst[qr * 128 + colq] = ss;
                pst[512 + qr * 128 + colq] = qq;
            }
            __syncthreads();
            if (tid < 128) {
                float ss = pst[tid] + pst[128 + tid] + pst[256 + tid] + pst[384 + tid];
                float qq = pst[512 + tid] + pst[640 + tid] + pst[768 + tid] + pst[896 + tid];
                float mean = ss * (1.0f / 256.0f);
                float var = qq * (1.0f / 256.0f) - mean * mean;
                float inv = rsqrtf(var + 1e-5f);
                float scl = GM[layer][tid] * inv;
                scv[tid] = scl;
                shv[tid] = BT[layer][tid] - mean * scl;  // linear bias cancels in BN
            }
            __syncthreads();

            // normalize + ReLU from regs, split bf16 hi/lo, store next A
            {
                char* hb = sm + OFF_AHI + tile * 32768;
                char* lb = sm + OFF_ALO + tile * 32768;
#pragma unroll
                for (int c8 = 0; c8 < 8; ++c8) {
                    int j0 = jbase + c8 * 8;
                    float f[8];
#pragma unroll
                    for (int i = 0; i < 8; ++i) {
                        float sc = scv[j0 + i];
                        float sh = shv[j0 + i];
                        f[i] = fmaxf(fmaf(__uint_as_float(d[c8 * 8 + i]), sc, sh), 0.f);
                    }
                    uint4 H, L;
                    split8(f, H, L);
                    uint32_t off = swb(rl, j0);
                    *(uint4*)(hb + off) = H;
                    *(uint4*)(lb + off) = L;
                }
            }
            FENCE_PROXY();
            __syncthreads();
        }
    }

    // ---- layer-3 epilogue ----
    if (is_c) {
#pragma unroll
        for (int q = 0; q < 16; ++q) {
            float4 bb = __ldg((const float4*)B3 + colhalf * 16 + q);
            float4 v;
            v.x = __uint_as_float(d[4 * q + 0]) + bb.x;
            v.y = __uint_as_float(d[4 * q + 1]) + bb.y;
            v.z = __uint_as_float(d[4 * q + 2]) + bb.z;
            v.w = __uint_as_float(d[4 * q + 3]) + bb.w;
            g_c_out[myrow * 32 + colhalf * 16 + q] = v;
        }
        __threadfence();
        __syncthreads();
        if (tid == 0) atomicExch(&g_flag, 1);
    } else {
        if (tid == 0) {
            while (atomicAdd(&g_flag, 0) == 0) { }
            __threadfence();
        }
        __syncthreads();
        float* op = out + ((size_t)myrow * 512 + slice) * 128 + jbase;
#pragma unroll
        for (int q = 0; q < 16; ++q) {
            float4 bb = __ldg((const float4*)B3 + colhalf * 16 + q);
            float4 cv = __ldcg(&g_c_out[myrow * 32 + colhalf * 16 + q]);
            float4 v;
            v.x = (__uint_as_float(d[4 * q + 0]) + bb.x) * cv.x;
            v.y = (__uint_as_float(d[4 * q + 1]) + bb.y) * cv.y;
            v.z = (__uint_as_float(d[4 * q + 2]) + bb.z) * cv.z;
            v.w = (__uint_as_float(d[4 * q + 3]) + bb.w) * cv.w;
            ((float4*)op)[q] = v;
        }
    }

    __syncthreads();
    if (tid == 0) MBARRIER_INVAL(smb + OFF_MBAR);
    __syncthreads();
    if (wid == 0) TCGEN05_DEALLOC(tmem, 256);

#else
    // ======================= FFMA2 fallback path =======================
    float* smf = (float*)smc;
    float* sm_act = smf;
    float* sm_wt  = smf + SM_ACT_F;
    float* sm_sc  = sm_wt + SM_WT_F;
    float* sm_sh  = sm_sc + 128;
    float* sm_gm  = sm_sh + 128;
    float* sm_bt  = sm_gm + 128;
    const int m = tid & 15;
    const int g = tid >> 4;

    {
        const float* src = is_c ? c : (s + (size_t)slice * 128);
        const size_t rstride = is_c ? (size_t)128 : (size_t)512 * 128;
        for (int idx = tid; idx < 256 * 32; idx += THREADS) {
            int r = idx >> 5;
            int kc = (idx & 31) << 2;
            float4 v = *(const float4*)(src + (size_t)r * rstride + kc);
            *(float4*)(sm_act + r * AP + kc) = v;
        }
    }
    load_wt(sm_wt, W1, tid);
    if (tid < 128) { sm_gm[tid] = G1[tid]; sm_bt[tid] = B1[tid]; }
    __syncthreads();

    u64 acc[8][4];
    fb_gemm(acc, sm_act, sm_wt, m, g);
    fb_bn_relu(acc, sm_act, sm_wt, sm_sc, sm_sh, sm_gm, sm_bt, m, g, tid);
    load_wt(sm_wt, W2, tid);
    if (tid < 128) { sm_gm[tid] = G2[tid]; sm_bt[tid] = B2[tid]; }
    __syncthreads();

    fb_gemm(acc, sm_act, sm_wt, m, g);
    fb_bn_relu(acc, sm_act, sm_wt, sm_sc, sm_sh, sm_gm, sm_bt, m, g, tid);
    load_wt(sm_wt, W3, tid);
    if (tid < 128) sm_bt[tid] = B3[tid];
    __syncthreads();

    fb_gemm(acc, sm_act, sm_wt, m, g);

    float* gco = (float*)g_c_out;
    if (is_c) {
#pragma unroll
        for (int p = 0; p < 4; ++p) {
            int j0 = 2 * m + 32 * p;
            float bb0 = sm_bt[j0], bb1 = sm_bt[j0 + 1];
#pragma unroll
            for (int i = 0; i < 8; ++i) {
                float lo, hi;
                unpack2(acc[i][p], lo, hi);
                float2 v; v.x = lo + bb0; v.y = hi + bb1;
                *(float2*)&gco[(g * 8 + i) * 128 + j0] = v;
            }
        }
        __threadfence();
        __syncthreads();
        if (tid == 0) atomicExch(&g_flag, 1);
    } else {
        if (tid == 0) {
            while (atomicAdd(&g_flag, 0) == 0) { }
            __threadfence();
        }
        __syncthreads();
#pragma unroll
        for (int p = 0; p < 4; ++p) {
            int j0 = 2 * m + 32 * p;
            float bb0 = sm_bt[j0], bb1 = sm_bt[j0 + 1];
#pragma unroll
            for (int i = 0; i < 8; ++i) {
                int r = g * 8 + i;
                float lo, hi;
                unpack2(acc[i][p], lo, hi);
                float2 cv = __ldcg((const float2*)&gco[r * 128 + j0]);
                float2 v;
                v.x = (lo + bb0) * cv.x;
                v.y = (hi + bb1) * cv.y;
                *(float2*)(out + ((size_t)r * 512 + slice) * 128 + j0) = v;
            }
        }
    }
#endif
}

// ---- Max-pool, stage 1: partial max over 64 slices each ----
__global__ void partial_max(const float* __restrict__ so) {
    int b = blockIdx.x >> 3;
    int seg = blockIdx.x & 7;
    int dcol = threadIdx.x;
    const float* p = so + ((size_t)b * 512 + seg * 64) * 128 + dcol;
    float mx = -3.402823466e38f;
#pragma unroll 16
    for (int i = 0; i < 64; ++i) mx = fmaxf(mx, p[(size_t)i * 128]);
    g_part[(size_t)blockIdx.x * 128 + dcol] = mx;
}

// ---- Max-pool, stage 2: reduce 8 partials; reset flag for graph replay ----
__global__ void final_max(float* __restrict__ agg) {
    if (blockIdx.x == 0 && threadIdx.x == 0) g_flag = 0;
    int idx = blockIdx.x * blockDim.x + threadIdx.x;
    int b = idx >> 7;
    int dcol = idx & 127;
    float mx = -3.402823466e38f;
#pragma unroll
    for (int seg = 0; seg < 8; ++seg)
        mx = fmaxf(mx, g_part[(size_t)(b * 8 + seg) * 128 + dcol]);
    agg[idx] = mx;
}

extern "C" void kernel_launch(void* const* d_in, const int* in_sizes, int n_in,
                              void* d_out, int out_size) {
    const float* s    = (const float*)d_in[0];
    const float* c    = (const float*)d_in[1];
    const float* sw1  = (const float*)d_in[2];
    const float* sg1  = (const float*)d_in[4];
    const float* sbe1 = (const float*)d_in[5];
    const float* sw2  = (const float*)d_in[6];
    const float* sg2  = (const float*)d_in[8];
    const float* sbe2 = (const float*)d_in[9];
    const float* sw3  = (const float*)d_in[10];
    const float* sb3  = (const float*)d_in[11];
    const float* cw1  = (const float*)d_in[12];
    const float* cg1  = (const float*)d_in[14];
    const float* cbe1 = (const float*)d_in[15];
    const float* cw2  = (const float*)d_in[16];
    const float* cg2  = (const float*)d_in[18];
    const float* cbe2 = (const float*)d_in[19];
    const float* cw3  = (const float*)d_in[20];
    const float* cb3  = (const float*)d_in[21];
    float* out = (float*)d_out;

    cudaFuncSetAttribute(mlp_kernel, cudaFuncAttributeMaxDynamicSharedMemorySize, SM_BYTES_MAX);

    mlp_kernel<<<513, THREADS, SM_BYTES_MAX>>>(s, c,
                                               sw1, sg1, sbe1, sw2, sg2, sbe2, sw3, sb3,
                                               cw1, cg1, cbe1, cw2, cg2, cbe2, cw3, cb3,
                                               out);

    float* agg = out + ((size_t)out_size - 256 * 128);
    partial_max<<<2048, 128>>>(out);
    final_max<<<128, 256>>>(agg);
}

// round 4
// speedup vs baseline: 3.2880x; 1.0920x over previous
#include <cuda_runtime.h>
#include <cuda_bf16.h>
#include <cstdint>

// CGBlock: per-slice 3-layer MLP (Linear->BN->ReLU x2 ->Linear), context gate,
// max-pool. B=256, S=512, D=128 fp32.
// tcgen05 bf16x3-split GEMMs (fp32 TMEM accum) on the sm_103a pass; FFMA2
// fallback on non-arch-specific passes (tcgen05 illegal there).

#define THREADS 512

#if defined(__CUDA_ARCH__) && (defined(__CUDA_ARCH_FEAT_SM103_ALL) || defined(__CUDA_ARCH_FEAT_SM100_ALL) || defined(__CUDA_ARCH_FEAT_SM101_ALL))
#define USE_TC 1
#else
#define USE_TC 0
#endif

// ---------------- shared device state ----------------
__device__ float4 g_c_out[256 * 32];
__device__ int g_flag = 0;
__device__ float4 g_part[1024 * 32];              // [256b x 4seg][32 col4]
__device__ uint4 g_wbuf[6][4096];                 // 6 matrices x 64KB (hi 32K | lo 32K), smem image

// ---------------- TC-path SMEM layout (bytes) ----------------
#define OFF_TMEM 0
#define OFF_MBAR 8
#define OFF_MBAR2 16
#define OFF_AHI  1024                 // A_hi: 2 tiles x 32768
#define OFF_ALO  (1024 + 65536)       // A_lo: 2 tiles x 32768
#define OFF_WHI  132096               // W hi 32768 | lo 32768 contiguous
#define OFF_WLO  164864
#define OFF_SC   197632
#define OFF_SH   198144
#define OFF_PST  198656               // f32[1024] partial stats
#define SM_TC_BYTES 202752

// ---------------- fallback SMEM layout (floats) ----------------
#define AP 132
#define WP 130
#define SM_ACT_F (256 * AP)
#define SM_WT_F  (128 * WP)
#define SM_FB_BYTES ((SM_ACT_F + SM_WT_F + 4 * 128) * 4)
#define SM_BYTES_MAX (SM_FB_BYTES > SM_TC_BYTES ? SM_FB_BYTES : SM_TC_BYTES)

// idesc kind::f16: c=F32, a=BF16, b=BF16, N=128, M=128
#define IDESC 0x08200490u

typedef unsigned long long u64;

__device__ __forceinline__ uint32_t smem_u32(const void* p) {
    uint32_t a;
    asm("{ .reg .u64 t; cvta.to.shared.u64 t, %1; cvt.u32.u64 %0, t; }" : "=r"(a) : "l"(p));
    return a;
}

// Blocked SW128 addr for bf16 tile [128r x 128k]: atoms 8r x 64 bf16.
__device__ __forceinline__ uint32_t swb(int rl, int j0) {
    uint32_t off = (uint32_t)((((rl >> 3) + ((j0 >> 6) << 4)) << 10) + ((rl & 7) << 7) + ((j0 & 63) << 1));
    return off ^ ((off >> 3) & 0x70);
}

// Fast split: hi = bf16-truncate (PRMT pack), lo = rn_bf16(x - hi).
__device__ __forceinline__ void split8f(const float* f, uint4& h, uint4& l) {
    uint32_t hh[4], ll[4];
#pragma unroll
    for (int i = 0; i < 4; ++i) {
        float x = f[2 * i], y = f[2 * i + 1];
        uint32_t bx = __float_as_uint(x), by = __float_as_uint(y);
        uint32_t hp;
        asm("prmt.b32 %0, %1, %2, 0x7632;" : "=r"(hp) : "r"(bx), "r"(by));
        hh[i] = hp;
        float lx = x - __uint_as_float(bx & 0xFFFF0000u);
        float ly = y - __uint_as_float(by & 0xFFFF0000u);
        uint32_t lp;
        asm("cvt.rn.bf16x2.f32 %0, %1, %2;" : "=r"(lp) : "f"(ly), "f"(lx));
        ll[i] = lp;
    }
    h = make_uint4(hh[0], hh[1], hh[2], hh[3]);
    l = make_uint4(ll[0], ll[1], ll[2], ll[3]);
}

// ---- prologue: split all 6 weight matrices into swizzled bf16 hi/lo images ----
__global__ void __launch_bounds__(512, 1)
presplit_w(const float* __restrict__ w0, const float* __restrict__ w1,
           const float* __restrict__ w2, const float* __restrict__ w3,
           const float* __restrict__ w4, const float* __restrict__ w5) {
    const float* W[6] = {w0, w1, w2, w3, w4, w5};
    const float* w = W[blockIdx.x];
    char* dst = (char*)&g_wbuf[blockIdx.x][0];
    for (int idx = threadIdx.x; idx < 128 * 16; idx += 512) {
        int row = idx >> 4;
        int ch = idx & 15;
        const float* p = w + row * 128 + ch * 8;
        float4 a = *(const float4*)p;
        float4 b = *(const float4*)(p + 4);
        float f[8] = {a.x, a.y, a.z, a.w, b.x, b.y, b.z, b.w};
        uint4 H, L;
        split8f(f, H, L);
        uint32_t off = swb(row, ch * 8);
        *(uint4*)(dst + off) = H;
        *(uint4*)(dst + 32768 + off) = L;
    }
}

#if USE_TC
// ---------------- tcgen05 PTX (arch-specific passes only) ----------------
__device__ __forceinline__ uint32_t elect_one_pred() {
    uint32_t pred;
    asm volatile("{\n\t.reg .pred p;\n\telect.sync _|p, 0xFFFFFFFF;\n\tselp.b32 %0, 1, 0, p;\n\t}"
                 : "=r"(pred));
    return pred;
}
#define TCGEN05_ALLOC(a, n) \
    asm volatile("tcgen05.alloc.cta_group::1.sync.aligned.shared::cta.b32 [%0], %1;" \
                 :: "r"((uint32_t)(a)), "r"((uint32_t)(n)) : "memory")
#define TCGEN05_DEALLOC(t, n) \
    asm volatile("tcgen05.dealloc.cta_group::1.sync.aligned.b32 %0, %1;" :: "r"(t), "r"((uint32_t)(n)))
#define TCGEN05_RELINQ() \
    asm volatile("tcgen05.relinquish_alloc_permit.cta_group::1.sync.aligned;")
#define TCGEN05_COMMIT(m) \
    asm volatile("tcgen05.commit.cta_group::1.mbarrier::arrive::one.shared::cluster.b64 [%0];" \
                 :: "r"((uint32_t)(m)) : "memory")
#define TCGEN05_WAIT_LD()  asm volatile("tcgen05.wait::ld.sync.aligned;" ::: "memory")
#define TCGEN05_FENCE_BEFORE() asm volatile("tcgen05.fence::before_thread_sync;" ::: "memory")
#define TCGEN05_FENCE_AFTER()  asm volatile("tcgen05.fence::after_thread_sync;" ::: "memory")
#define FENCE_PROXY() asm volatile("fence.proxy.async.shared::cta;" ::: "memory")
#define MBARRIER_INIT(m, c) \
    asm volatile("mbarrier.init.shared.b64 [%0], %1;" :: "r"((uint32_t)(m)), "r"((uint32_t)(c)) : "memory")
#define MBARRIER_INVAL(m) \
    asm volatile("mbarrier.inval.shared.b64 [%0];" :: "r"((uint32_t)(m)) : "memory")
#define MBARRIER_WAIT_PARITY(mb, ph) do { \
    uint32_t _m = (uint32_t)(mb); uint32_t _p = (uint32_t)(ph); uint32_t _d; \
    asm volatile("{\n\t.reg .pred p;\n\t" \
        "mbarrier.try_wait.parity.acquire.cta.shared::cta.b64 p, [%1], %2;\n\t" \
        "selp.b32 %0, 1, 0, p;\n\t}" : "=r"(_d) : "r"(_m), "r"(_p) : "memory"); \
    if (!_d) { \
        asm volatile("{\n\t.reg .pred P1;\n\t" \
            "WAIT_LOOP_%=:\n\t" \
            "mbarrier.try_wait.parity.acquire.cta.shared::cta.b64 P1, [%0], %1, 0x989680;\n\t" \
            "@P1 bra.uni WAIT_DONE_%=;\n\t" \
            "bra.uni WAIT_LOOP_%=;\n\t" \
            "WAIT_DONE_%=:\n\t}" :: "r"(_m), "r"(_p) : "memory"); \
    } \
} while (0)
#define TCGEN05_LD_X32(r, a) \
    asm volatile("tcgen05.ld.sync.aligned.32x32b.x32.b32 " \
        "{%0, %1, %2, %3, %4, %5, %6, %7, %8, %9, %10, %11, %12, %13, %14, %15, " \
        " %16, %17, %18, %19, %20, %21, %22, %23, %24, %25, %26, %27, %28, %29, %30, %31}, [%32];" \
        : "=r"((r)[0]),  "=r"((r)[1]),  "=r"((r)[2]),  "=r"((r)[3]), \
          "=r"((r)[4]),  "=r"((r)[5]),  "=r"((r)[6]),  "=r"((r)[7]), \
          "=r"((r)[8]),  "=r"((r)[9]),  "=r"((r)[10]), "=r"((r)[11]), \
          "=r"((r)[12]), "=r"((r)[13]), "=r"((r)[14]), "=r"((r)[15]), \
          "=r"((r)[16]), "=r"((r)[17]), "=r"((r)[18]), "=r"((r)[19]), \
          "=r"((r)[20]), "=r"((r)[21]), "=r"((r)[22]), "=r"((r)[23]), \
          "=r"((r)[24]), "=r"((r)[25]), "=r"((r)[26]), "=r"((r)[27]), \
          "=r"((r)[28]), "=r"((r)[29]), "=r"((r)[30]), "=r"((r)[31]) \
        : "r"(a))

__device__ __forceinline__ void mma_bf16_ss(uint32_t d, uint64_t a, uint64_t b, uint32_t en) {
    asm volatile(
        "{\n\t.reg .pred p;\n\tsetp.ne.u32 p, %5, 0;\n\t"
        "tcgen05.mma.cta_group::1.kind::f16 [%0], %1, %2, %3, {%4, %4, %4, %4}, p;\n\t}"
        :: "r"(d), "l"(a), "l"(b), "r"(IDESC), "r"(0u), "r"(en) : "memory");
}
__device__ __forceinline__ uint64_t make_desc(uint32_t addr) {
    const uint64_t base = (uint64_t(2) << 61) | (uint64_t(1) << 46) |
                          (uint64_t(64) << 32) | (uint64_t(1) << 16);
    return base | ((uint64_t)(addr >> 4) & 0x3FFF);
}
#endif  // USE_TC

// ---------------- fallback (FFMA2) helpers ----------------
__device__ __forceinline__ u64 pack2(float x) {
    u64 r;
    unsigned int xi = __float_as_uint(x);
    asm("mov.b64 %0, {%1, %1};" : "=l"(r) : "r"(xi));
    return r;
}
__device__ __forceinline__ void fma2(u64& d, u64 a, u64 b) {
    asm("fma.rn.f32x2 %0, %1, %2, %0;" : "+l"(d) : "l"(a), "l"(b));
}
__device__ __forceinline__ void unpack2(u64 v, float& lo, float& hi) {
    unsigned int a, b;
    asm("mov.b64 {%0, %1}, %2;" : "=r"(a), "=r"(b) : "l"(v));
    lo = __uint_as_float(a);
    hi = __uint_as_float(b);
}
__device__ __forceinline__ void load_wt(float* sm_wt, const float* __restrict__ w, int tid) {
    for (int idx = tid; idx < 128 * 32; idx += THREADS) {
        int j = idx >> 5;
        int kc = (idx & 31) << 2;
        float4 v = *(const float4*)(w + j * 128 + kc);
        sm_wt[(kc + 0) * WP + j] = v.x;
        sm_wt[(kc + 1) * WP + j] = v.y;
        sm_wt[(kc + 2) * WP + j] = v.z;
        sm_wt[(kc + 3) * WP + j] = v.w;
    }
}
__device__ __forceinline__ void fb_gemm(u64 (&acc)[8][4], const float* sm_act,
                                        const float* sm_wt, int m, int g) {
#pragma unroll
    for (int i = 0; i < 8; ++i)
#pragma unroll
        for (int p = 0; p < 4; ++p) acc[i][p] = 0ULL;
    const float* a0 = sm_act + (g * 8) * AP;
#pragma unroll 2
    for (int k = 0; k < 128; ++k) {
        const float* wk = sm_wt + k * WP + 2 * m;
        u64 b0 = *(const u64*)(wk);
        u64 b1 = *(const u64*)(wk + 32);
        u64 b2 = *(const u64*)(wk + 64);
        u64 b3 = *(const u64*)(wk + 96);
#pragma unroll
        for (int i = 0; i < 8; ++i) {
            u64 a2 = pack2(a0[i * AP + k]);
            fma2(acc[i][0], a2, b0);
            fma2(acc[i][1], a2, b1);
            fma2(acc[i][2], a2, b2);
            fma2(acc[i][3], a2, b3);
        }
    }
}
__device__ __forceinline__ void fb_bn_relu(u64 (&acc)[8][4], float* sm_act, float* sm_scr,
                                           float* sm_sc, float* sm_sh,
                                           const float* sm_gm, const float* sm_bt,
                                           int m, int g, int tid) {
    float* ssum = sm_scr;
    float* ssq  = sm_scr + 32 * 128;
    __syncthreads();
#pragma unroll
    for (int p = 0; p < 4; ++p) {
        int j0 = 2 * m + 32 * p;
        float s0 = 0.f, q0 = 0.f, s1 = 0.f, q1 = 0.f;
#pragma unroll
        for (int i = 0; i < 8; ++i) {
            float lo, hi;
            unpack2(acc[i][p], lo, hi);
            s0 += lo; q0 += lo * lo;
            s1 += hi; q1 += hi * hi;
        }
        ssum[g * 128 + j0] = s0;     ssq[g * 128 + j0] = q0;
        ssum[g * 128 + j0 + 1] = s1; ssq[g * 128 + j0 + 1] = q1;
    }
    __syncthreads();
    if (tid < 128) {
        float s = 0.f, q = 0.f;
#pragma unroll
        for (int gg = 0; gg < 32; ++gg) {
            s += ssum[gg * 128 + tid];
            q += ssq[gg * 128 + tid];
        }
        float mean = s * (1.0f / 256.0f);
        float var  = q * (1.0f / 256.0f) - mean * mean;
        float inv  = rsqrtf(var + 1e-5f);
        float sc   = sm_gm[tid] * inv;
        sm_sc[tid] = sc;
        sm_sh[tid] = sm_bt[tid] - mean * sc;
    }
    __syncthreads();
#pragma unroll
    for (int p = 0; p < 4; ++p) {
        int j0 = 2 * m + 32 * p;
        float sc0 = sm_sc[j0], sh0 = sm_sh[j0];
        float sc1 = sm_sc[j0 + 1], sh1 = sm_sh[j0 + 1];
#pragma unroll
        for (int i = 0; i < 8; ++i) {
            float lo, hi;
            unpack2(acc[i][p], lo, hi);
            float2 v;
            v.x = fmaxf(fmaf(lo, sc0, sh0), 0.0f);
            v.y = fmaxf(fmaf(hi, sc1, sh1), 0.0f);
            *(float2*)(sm_act + (g * 8 + i) * AP + j0) = v;
        }
    }
}

// ============================= the MLP kernel =============================
__global__ void __launch_bounds__(THREADS, 1)
mlp_kernel(const float* __restrict__ s, const float* __restrict__ c,
           const float* __restrict__ sw1, const float* __restrict__ sg1, const float* __restrict__ sbe1,
           const float* __restrict__ sw2, const float* __restrict__ sg2, const float* __restrict__ sbe2,
           const float* __restrict__ sw3, const float* __restrict__ sb3,
           const float* __restrict__ cw1, const float* __restrict__ cg1, const float* __restrict__ cbe1,
           const float* __restrict__ cw2, const float* __restrict__ cg2, const float* __restrict__ cbe2,
           const float* __restrict__ cw3, const float* __restrict__ cb3,
           float* __restrict__ out) {
    extern __shared__ char smc[];
    const int tid = threadIdx.x;
    const bool is_c = (blockIdx.x == 0);
    const int slice = (int)blockIdx.x - 1;

    const float *G1, *G2, *B1, *B2, *B3;
    if (is_c) { G1=cg1; G2=cg2; B1=cbe1; B2=cbe2; B3=cb3; }
    else      { G1=sg1; G2=sg2; B1=sbe1; B2=sbe2; B3=sb3; }
    const int wbase = is_c ? 3 : 0;

#if USE_TC
    // ======================= tcgen05 path =======================
    char* sm = smc;
    const uint32_t smb = smem_u32(sm);
    const int wid = tid >> 5;
    const int lane = tid & 31;

    if (wid == 0) {
        TCGEN05_ALLOC(smb + OFF_TMEM, 256);
        TCGEN05_RELINQ();
    }
    if (tid == 0) {
        MBARRIER_INIT(smb + OFF_MBAR, 1);
        MBARRIER_INIT(smb + OFF_MBAR2, 1);
    }
    __syncthreads();
    uint32_t tmem;
    asm volatile("ld.shared.b32 %0, [%1];" : "=r"(tmem) : "r"(smb + OFF_TMEM));

    // Pre-load BN params into regs (tid<128 lanes used in combine stage)
    float gmr0 = 0.f, gmr1 = 0.f, btr0 = 0.f, btr1 = 0.f;
    if (tid < 128) {
        gmr0 = G1[tid]; btr0 = B1[tid];
        gmr1 = G2[tid]; btr1 = B2[tid];
    }

    // Stage input slice: fp32 -> bf16 hi/lo split into swizzled A tiles
    {
        const float* src = is_c ? c : (s + (size_t)slice * 128);
        size_t rstride = is_c ? (size_t)128 : (size_t)512 * 128;
        for (int idx = tid; idx < 256 * 16; idx += THREADS) {
            int row = idx >> 4;
            int ch = idx & 15;
            const float* p = src + (size_t)row * rstride + ch * 8;
            float4 a = *(const float4*)p;
            float4 b = *(const float4*)(p + 4);
            float f[8] = {a.x, a.y, a.z, a.w, b.x, b.y, b.z, b.w};
            uint4 H, L;
            split8f(f, H, L);
            int t = row >> 7;
            uint32_t off = swb(row & 127, ch * 8) + t * 32768;
            *(uint4*)(sm + OFF_AHI + off) = H;
            *(uint4*)(sm + OFF_ALO + off) = L;
        }
    }
    // Copy W1 image (pre-split, pre-swizzled): straight 64KB copy
    {
        const uint4* srcw = &g_wbuf[wbase][0];
        uint4* dstw = (uint4*)(sm + OFF_WHI);
        for (int i = tid; i < 4096; i += THREADS) dstw[i] = srcw[i];
    }
    FENCE_PROXY();
    __syncthreads();

    // warp mapping: tile = wid>>3, colhalf = (wid>>2)&1, rowgrp = wid&3
    const int tile = wid >> 3;
    const int colhalf = (wid >> 2) & 1;
    const int rowgrp = wid & 3;
    const int myrow = tile * 128 + rowgrp * 32 + lane;
    const int rl = myrow & 127;
    const int jbase = colhalf * 64;

    // scratch quarters: q0->AHI t0, q1->ALO t0, q2->AHI t1, q3->ALO t1
    auto qbase = [&](int q) -> uint32_t {
        return ((q & 1) ? OFF_ALO : OFF_AHI) + ((q >> 1) ? 32768u : 0u);
    };

    float* scv = (float*)(sm + OFF_SC);
    float* shv = (float*)(sm + OFF_SH);
    float* pst = (float*)(sm + OFF_PST);

    uint32_t d[64];

#pragma unroll 1
    for (int layer = 0; layer < 3; ++layer) {
        // ---- MMA: per tile, 3 passes (AhBh, AhBl, AlBh) x 8 k-steps ----
        if (wid == 0) {
            if (elect_one_pred()) {
                uint64_t bh = make_desc(smb + OFF_WHI);
                uint64_t bl = make_desc(smb + OFF_WLO);
#pragma unroll
                for (int T = 0; T < 2; ++T) {
                    uint64_t ah = make_desc(smb + OFF_AHI + T * 32768);
                    uint64_t al = make_desc(smb + OFF_ALO + T * 32768);
#pragma unroll
                    for (int pass = 0; pass < 3; ++pass) {
                        uint64_t ad = (pass == 2) ? al : ah;
                        uint64_t bd = (pass == 1) ? bl : bh;
#pragma unroll
                        for (int ks = 0; ks < 8; ++ks) {
                            uint32_t off = ((ks >> 2) << 10) + ((ks & 3) << 1);
                            mma_bf16_ss(tmem + T * 128, ad + off, bd + off,
                                        (pass | ks) ? 1u : 0u);
                        }
                    }
                    TCGEN05_COMMIT(smb + (T == 0 ? OFF_MBAR : OFF_MBAR2));
                }
            }
        }
        // Each tile group waits only on its own barrier (tile0 overlaps tile1 MMA)
        MBARRIER_WAIT_PARITY(smb + (tile == 0 ? OFF_MBAR : OFF_MBAR2), layer & 1);
        TCGEN05_FENCE_AFTER();

        {
            uint32_t tb = tmem + tile * 128 + jbase;
            TCGEN05_LD_X32(d + 0, tb + 0);
            TCGEN05_LD_X32(d + 32, tb + 32);
        }
        // tile1 group copies next-layer weights (all MMAs done once mbar2 fired);
        // overlaps LDTM completion.
        if (tile == 1 && layer < 2) {
            const uint4* srcw = &g_wbuf[wbase + layer + 1][0];
            uint4* dstw = (uint4*)(sm + OFF_WHI);
            int t256 = tid - 256;
            for (int i = t256; i < 4096; i += 256) dstw[i] = srcw[i];
        }
        TCGEN05_WAIT_LD();
        TCGEN05_FENCE_BEFORE();

        if (layer < 2) {
            // Write my row's 64 cols to fp32 scratch (quartered into my tile's
            // consumed A regions only — safe while other tile's MMA may still run)
            {
                float4* mr = (float4*)(sm + qbase(myrow >> 6) + (uint32_t)(myrow & 63) * 512 +
                                       (uint32_t)jbase * 4);
#pragma unroll
                for (int q = 0; q < 16; ++q) {
                    float4 v;
                    v.x = __uint_as_float(d[4 * q + 0]);
                    v.y = __uint_as_float(d[4 * q + 1]);
                    v.z = __uint_as_float(d[4 * q + 2]);
                    v.w = __uint_as_float(d[4 * q + 3]);
                    mr[q] = v;
                }
            }
            __syncthreads();

            // BN stats: 512 threads -> (col, quarter) partials -> 128 combine
            {
                int colq = tid & 127;
                int qr = tid >> 7;
                const float* bp = (const float*)(sm + qbase(qr)) + colq;
                float ss = 0.f, qq = 0.f;
#pragma unroll 8
                for (int r = 0; r < 64; ++r) {
                    float v = bp[(size_t)r * 128];
                    ss += v;
                    qq = fmaf(v, v, qq);
                }
                pst[qr * 128 + colq] = ss;
                pst[512 + qr * 128 + colq] = qq;
            }
            __syncthreads();
            if (tid < 128) {
                float ss = pst[tid] + pst[128 + tid] + pst[256 + tid] + pst[384 + tid];
                float qq = pst[512 + tid] + pst[640 + tid] + pst[768 + tid] + pst[896 + tid];
                float mean = ss * (1.0f / 256.0f);
                float var = qq * (1.0f / 256.0f) - mean * mean;
                float inv = rsqrtf(var + 1e-5f);
                float gm = layer ? gmr1 : gmr0;
                float bt = layer ? btr1 : btr0;
                float scl = gm * inv;
                scv[tid] = scl;
                shv[tid] = bt - mean * scl;   // linear bias cancels in BN
            }
            __syncthreads();

            // Normalize + ReLU from regs, split bf16 hi/lo, store next A
            {
                char* hb = sm + OFF_AHI + tile * 32768;
                char* lb = sm + OFF_ALO + tile * 32768;
#pragma unroll
                for (int c8 = 0; c8 < 8; ++c8) {
                    int j0 = jbase + c8 * 8;
                    float f[8];
#pragma unroll
                    for (int i = 0; i < 8; ++i) {
                        f[i] = fmaxf(fmaf(__uint_as_float(d[c8 * 8 + i]), scv[j0 + i], shv[j0 + i]), 0.f);
                    }
                    uint4 H, L;
                    split8f(f, H, L);
                    uint32_t off = swb(rl, j0);
                    *(uint4*)(hb + off) = H;
                    *(uint4*)(lb + off) = L;
                }
            }
            FENCE_PROXY();
            __syncthreads();
        }
    }

    // ---- layer-3 epilogue: +b3, gate, write ----
    if (is_c) {
#pragma unroll
        for (int q = 0; q < 16; ++q) {
            float4 bb = __ldg((const float4*)B3 + colhalf * 16 + q);
            float4 v;
            v.x = __uint_as_float(d[4 * q + 0]) + bb.x;
            v.y = __uint_as_float(d[4 * q + 1]) + bb.y;
            v.z = __uint_as_float(d[4 * q + 2]) + bb.z;
            v.w = __uint_as_float(d[4 * q + 3]) + bb.w;
            g_c_out[myrow * 32 + colhalf * 16 + q] = v;
        }
        __threadfence();
        __syncthreads();
        if (tid == 0) atomicExch(&g_flag, 1);
    } else {
        if (tid == 0) {
            while (atomicAdd(&g_flag, 0) == 0) { }
            __threadfence();
        }
        __syncthreads();
        float* op = out + ((size_t)myrow * 512 + slice) * 128 + jbase;
#pragma unroll
        for (int q = 0; q < 16; ++q) {
            float4 bb = __ldg((const float4*)B3 + colhalf * 16 + q);
            float4 cv = __ldcg(&g_c_out[myrow * 32 + colhalf * 16 + q]);
            float4 v;
            v.x = (__uint_as_float(d[4 * q + 0]) + bb.x) * cv.x;
            v.y = (__uint_as_float(d[4 * q + 1]) + bb.y) * cv.y;
            v.z = (__uint_as_float(d[4 * q + 2]) + bb.z) * cv.z;
            v.w = (__uint_as_float(d[4 * q + 3]) + bb.w) * cv.w;
            ((float4*)op)[q] = v;
        }
    }

    __syncthreads();
    if (tid == 0) {
        MBARRIER_INVAL(smb + OFF_MBAR);
        MBARRIER_INVAL(smb + OFF_MBAR2);
    }
    __syncthreads();
    if (wid == 0) TCGEN05_DEALLOC(tmem, 256);

#else
    // ======================= FFMA2 fallback path =======================
    const float *W1, *W2, *W3;
    if (is_c) { W1=cw1; W2=cw2; W3=cw3; }
    else      { W1=sw1; W2=sw2; W3=sw3; }
    float* smf = (float*)smc;
    float* sm_act = smf;
    float* sm_wt  = smf + SM_ACT_F;
    float* sm_sc  = sm_wt + SM_WT_F;
    float* sm_sh  = sm_sc + 128;
    float* sm_gm  = sm_sh + 128;
    float* sm_bt  = sm_gm + 128;
    const int m = tid & 15;
    const int g = tid >> 4;

    {
        const float* src = is_c ? c : (s + (size_t)slice * 128);
        const size_t rstride = is_c ? (size_t)128 : (size_t)512 * 128;
        for (int idx = tid; idx < 256 * 32; idx += THREADS) {
            int r = idx >> 5;
            int kc = (idx & 31) << 2;
            float4 v = *(const float4*)(src + (size_t)r * rstride + kc);
            *(float4*)(sm_act + r * AP + kc) = v;
        }
    }
    load_wt(sm_wt, W1, tid);
    if (tid < 128) { sm_gm[tid] = G1[tid]; sm_bt[tid] = B1[tid]; }
    __syncthreads();

    u64 acc[8][4];
    fb_gemm(acc, sm_act, sm_wt, m, g);
    fb_bn_relu(acc, sm_act, sm_wt, sm_sc, sm_sh, sm_gm, sm_bt, m, g, tid);
    load_wt(sm_wt, W2, tid);
    if (tid < 128) { sm_gm[tid] = G2[tid]; sm_bt[tid] = B2[tid]; }
    __syncthreads();

    fb_gemm(acc, sm_act, sm_wt, m, g);
    fb_bn_relu(acc, sm_act, sm_wt, sm_sc, sm_sh, sm_gm, sm_bt, m, g, tid);
    load_wt(sm_wt, W3, tid);
    if (tid < 128) sm_bt[tid] = B3[tid];
    __syncthreads();

    fb_gemm(acc, sm_act, sm_wt, m, g);

    float* gco = (float*)g_c_out;
    if (is_c) {
#pragma unroll
        for (int p = 0; p < 4; ++p) {
            int j0 = 2 * m + 32 * p;
            float bb0 = sm_bt[j0], bb1 = sm_bt[j0 + 1];
#pragma unroll
            for (int i = 0; i < 8; ++i) {
                float lo, hi;
                unpack2(acc[i][p], lo, hi);
                float2 v; v.x = lo + bb0; v.y = hi + bb1;
                *(float2*)&gco[(g * 8 + i) * 128 + j0] = v;
            }
        }
        __threadfence();
        __syncthreads();
        if (tid == 0) atomicExch(&g_flag, 1);
    } else {
        if (tid == 0) {
            while (atomicAdd(&g_flag, 0) == 0) { }
            __threadfence();
        }
        __syncthreads();
#pragma unroll
        for (int p = 0; p < 4; ++p) {
            int j0 = 2 * m + 32 * p;
            float bb0 = sm_bt[j0], bb1 = sm_bt[j0 + 1];
#pragma unroll
            for (int i = 0; i < 8; ++i) {
                int r = g * 8 + i;
                float lo, hi;
                unpack2(acc[i][p], lo, hi);
                float2 cv = __ldcg((const float2*)&gco[r * 128 + j0]);
                float2 v;
                v.x = (lo + bb0) * cv.x;
                v.y = (hi + bb1) * cv.y;
                *(float2*)(out + ((size_t)r * 512 + slice) * 128 + j0) = v;
            }
        }
    }
#endif
}

// ---- Max-pool stage 1: grid 1024 = b(256) x seg(4, 128 slices each), 256 thr ----
__global__ void __launch_bounds__(256, 8)
partial_max(const float* __restrict__ so) {
    __shared__ float4 red[8][32];
    int b = blockIdx.x >> 2;
    int seg = blockIdx.x & 3;
    int c4 = threadIdx.x & 31;
    int sub = threadIdx.x >> 5;   // 8 subs x 16 slices
    const float4* p = (const float4*)(so + ((size_t)b * 512 + seg * 128 + sub * 16) * 128) + c4;
    float4 mx = make_float4(-3.4e38f, -3.4e38f, -3.4e38f, -3.4e38f);
#pragma unroll 16
    for (int i = 0; i < 16; ++i) {
        float4 v = p[(size_t)i * 32];
        mx.x = fmaxf(mx.x, v.x); mx.y = fmaxf(mx.y, v.y);
        mx.z = fmaxf(mx.z, v.z); mx.w = fmaxf(mx.w, v.w);
    }
    red[sub][c4] = mx;
    __syncthreads();
    if (threadIdx.x < 32) {
        float4 r = red[0][c4];
#pragma unroll
        for (int ss = 1; ss < 8; ++ss) {
            float4 v = red[ss][c4];
            r.x = fmaxf(r.x, v.x); r.y = fmaxf(r.y, v.y);
            r.z = fmaxf(r.z, v.z); r.w = fmaxf(r.w, v.w);
        }
        g_part[(size_t)blockIdx.x * 32 + c4] = r;
    }
}

// ---- Max-pool stage 2: 32 CTAs x 256; also reset flag for graph replay ----
__global__ void final_max(float* __restrict__ agg) {
    if (blockIdx.x == 0 && threadIdx.x == 0) g_flag = 0;
    int idx = blockIdx.x * 256 + threadIdx.x;   // 0..8191 = b*32 + c4
    int b = idx >> 5;
    int c4 = idx & 31;
    float4 r = g_part[(size_t)(b * 4) * 32 + c4];
#pragma unroll
    for (int seg = 1; seg < 4; ++seg) {
        float4 v = g_part[(size_t)(b * 4 + seg) * 32 + c4];
        r.x = fmaxf(r.x, v.x); r.y = fmaxf(r.y, v.y);
        r.z = fmaxf(r.z, v.z); r.w = fmaxf(r.w, v.w);
    }
    ((float4*)agg)[idx] = r;
}

extern "C" void kernel_launch(void* const* d_in, const int* in_sizes, int n_in,
                              void* d_out, int out_size) {
    const float* s    = (const float*)d_in[0];
    const float* c    = (const float*)d_in[1];
    const float* sw1  = (const float*)d_in[2];
    const float* sg1  = (const float*)d_in[4];
    const float* sbe1 = (const float*)d_in[5];
    const float* sw2  = (const float*)d_in[6];
    const float* sg2  = (const float*)d_in[8];
    const float* sbe2 = (const float*)d_in[9];
    const float* sw3  = (const float*)d_in[10];
    const float* sb3  = (const float*)d_in[11];
    const float* cw1  = (const float*)d_in[12];
    const float* cg1  = (const float*)d_in[14];
    const float* cbe1 = (const float*)d_in[15];
    const float* cw2  = (const float*)d_in[16];
    const float* cg2  = (const float*)d_in[18];
    const float* cbe2 = (const float*)d_in[19];
    const float* cw3  = (const float*)d_in[20];
    const float* cb3  = (const float*)d_in[21];
    float* out = (float*)d_out;

    cudaFuncSetAttribute(mlp_kernel, cudaFuncAttributeMaxDynamicSharedMemorySize, SM_BYTES_MAX);

    presplit_w<<<6, 512>>>(sw1, sw2, sw3, cw1, cw2, cw3);

    mlp_kernel<<<513, THREADS, SM_BYTES_MAX>>>(s, c,
                                               sw1, sg1, sbe1, sw2, sg2, sbe2, sw3, sb3,
                                               cw1, cg1, cbe1, cw2, cg2, cbe2, cw3, cb3,
                                               out);

    float* agg = out + ((size_t)out_size - 256 * 128);
    partial_max<<<1024, 256>>>(out);
    final_max<<<32, 256>>>(agg);
}

// round 6
// speedup vs baseline: 3.8697x; 1.1769x over previous
#include <cuda_runtime.h>
#include <cuda_bf16.h>
#include <cstdint>

// CGBlock: per-slice 3-layer MLP (Linear->BN->ReLU x2 ->Linear), context gate,
// max-pool. B=256, S=512, D=128 fp32.
// tcgen05 bf16x3-split GEMMs (fp32 TMEM accum) on the sm_103a pass; FFMA2
// fallback on non-arch-specific passes. 1024 threads/CTA for latency hiding;
// BN stats via warp-shuffle butterflies (no smem scratch round-trip).

#define THREADS 1024

#if defined(__CUDA_ARCH__) && (defined(__CUDA_ARCH_FEAT_SM103_ALL) || defined(__CUDA_ARCH_FEAT_SM100_ALL) || defined(__CUDA_ARCH_FEAT_SM101_ALL))
#define USE_TC 1
#else
#define USE_TC 0
#endif

// ---------------- shared device state ----------------
__device__ float4 g_c_out[256 * 32];
__device__ int g_flag = 0;
__device__ float4 g_part[1024 * 32];
__device__ uint4 g_wbuf[6][4096];   // 6 matrices x 64KB (hi 32K | lo 32K), smem image

// ---------------- TC-path SMEM layout (bytes) ----------------
#define OFF_TMEM 0
#define OFF_MBAR 8
#define OFF_MBAR2 16
#define OFF_AHI  1024                 // A_hi: 2 tiles x 32768
#define OFF_ALO  66560                // A_lo: 2 tiles x 32768
#define OFF_WHI  132096               // W hi 32768
#define OFF_WLO  164864               // W lo 32768
#define OFF_SC   197632               // BN scale f32[128]
#define OFF_SH   198144               // BN shift f32[128]
#define OFF_PST  198656               // f32[2048]: 1024 sum + 1024 sumsq
#define SM_TC_BYTES 206848

// ---------------- fallback SMEM layout (floats) ----------------
#define AP 132
#define WP 130
#define SM_ACT_F (256 * AP)
#define SM_WT_F  (128 * WP)
#define SM_FB_BYTES ((SM_ACT_F + SM_WT_F + 4 * 128) * 4)
#define SM_BYTES_MAX (SM_FB_BYTES > SM_TC_BYTES ? SM_FB_BYTES : SM_TC_BYTES)

// idesc kind::f16: c=F32, a=BF16, b=BF16, N=128, M=128
#define IDESC 0x08200490u

typedef unsigned long long u64;

__device__ __forceinline__ uint32_t smem_u32(const void* p) {
    uint32_t a;
    asm("{ .reg .u64 t; cvta.to.shared.u64 t, %1; cvt.u32.u64 %0, t; }" : "=r"(a) : "l"(p));
    return a;
}

// Blocked SW128 addr for bf16 tile [128r x 128k]: atoms 8r x 64 bf16.
__device__ __forceinline__ uint32_t swb(int rl, int j0) {
    uint32_t off = (uint32_t)((((rl >> 3) + ((j0 >> 6) << 4)) << 10) + ((rl & 7) << 7) + ((j0 & 63) << 1));
    return off ^ ((off >> 3) & 0x70);
}

// Fast split: hi = bf16-truncate (PRMT pack), lo = rn_bf16(x - hi).
__device__ __forceinline__ void split8f(const float* f, uint4& h, uint4& l) {
    uint32_t hh[4], ll[4];
#pragma unroll
    for (int i = 0; i < 4; ++i) {
        float x = f[2 * i], y = f[2 * i + 1];
        uint32_t bx = __float_as_uint(x), by = __float_as_uint(y);
        uint32_t hp;
        asm("prmt.b32 %0, %1, %2, 0x7632;" : "=r"(hp) : "r"(bx), "r"(by));
        hh[i] = hp;
        float lx = x - __uint_as_float(bx & 0xFFFF0000u);
        float ly = y - __uint_as_float(by & 0xFFFF0000u);
        uint32_t lp;
        asm("cvt.rn.bf16x2.f32 %0, %1, %2;" : "=r"(lp) : "f"(ly), "f"(lx));
        ll[i] = lp;
    }
    h = make_uint4(hh[0], hh[1], hh[2], hh[3]);
    l = make_uint4(ll[0], ll[1], ll[2], ll[3]);
}

// ---- prologue: split all 6 weight matrices into swizzled bf16 hi/lo images ----
__global__ void __launch_bounds__(512, 1)
presplit_w(const float* __restrict__ w0, const float* __restrict__ w1,
           const float* __restrict__ w2, const float* __restrict__ w3,
           const float* __restrict__ w4, const float* __restrict__ w5) {
    const float* W[6] = {w0, w1, w2, w3, w4, w5};
    const float* w = W[blockIdx.x];
    char* dst = (char*)&g_wbuf[blockIdx.x][0];
    for (int idx = threadIdx.x; idx < 128 * 16; idx += 512) {
        int row = idx >> 4;
        int ch = idx & 15;
        const float* p = w + row * 128 + ch * 8;
        float4 a = *(const float4*)p;
        float4 b = *(const float4*)(p + 4);
        float f[8] = {a.x, a.y, a.z, a.w, b.x, b.y, b.z, b.w};
        uint4 H, L;
        split8f(f, H, L);
        uint32_t off = swb(row, ch * 8);
        *(uint4*)(dst + off) = H;
        *(uint4*)(dst + 32768 + off) = L;
    }
}

#if USE_TC
// ---------------- tcgen05 PTX (arch-specific passes only) ----------------
__device__ __forceinline__ uint32_t elect_one_pred() {
    uint32_t pred;
    asm volatile("{\n\t.reg .pred p;\n\telect.sync _|p, 0xFFFFFFFF;\n\tselp.b32 %0, 1, 0, p;\n\t}"
                 : "=r"(pred));
    return pred;
}
#define TCGEN05_ALLOC(a, n) \
    asm volatile("tcgen05.alloc.cta_group::1.sync.aligned.shared::cta.b32 [%0], %1;" \
                 :: "r"((uint32_t)(a)), "r"((uint32_t)(n)) : "memory")
#define TCGEN05_DEALLOC(t, n) \
    asm volatile("tcgen05.dealloc.cta_group::1.sync.aligned.b32 %0, %1;" :: "r"(t), "r"((uint32_t)(n)))
#define TCGEN05_RELINQ() \
    asm volatile("tcgen05.relinquish_alloc_permit.cta_group::1.sync.aligned;")
#define TCGEN05_COMMIT(m) \
    asm volatile("tcgen05.commit.cta_group::1.mbarrier::arrive::one.shared::cluster.b64 [%0];" \
                 :: "r"((uint32_t)(m)) : "memory")
#define TCGEN05_WAIT_LD()  asm volatile("tcgen05.wait::ld.sync.aligned;" ::: "memory")
#define TCGEN05_FENCE_BEFORE() asm volatile("tcgen05.fence::before_thread_sync;" ::: "memory")
#define TCGEN05_FENCE_AFTER()  asm volatile("tcgen05.fence::after_thread_sync;" ::: "memory")
#define FENCE_PROXY() asm volatile("fence.proxy.async.shared::cta;" ::: "memory")
#define MBARRIER_INIT(m, c) \
    asm volatile("mbarrier.init.shared.b64 [%0], %1;" :: "r"((uint32_t)(m)), "r"((uint32_t)(c)) : "memory")
#define MBARRIER_INVAL(m) \
    asm volatile("mbarrier.inval.shared.b64 [%0];" :: "r"((uint32_t)(m)) : "memory")
#define MBARRIER_WAIT_PARITY(mb, ph) do { \
    uint32_t _m = (uint32_t)(mb); uint32_t _p = (uint32_t)(ph); uint32_t _d; \
    asm volatile("{\n\t.reg .pred p;\n\t" \
        "mbarrier.try_wait.parity.acquire.cta.shared::cta.b64 p, [%1], %2;\n\t" \
        "selp.b32 %0, 1, 0, p;\n\t}" : "=r"(_d) : "r"(_m), "r"(_p) : "memory"); \
    if (!_d) { \
        asm volatile("{\n\t.reg .pred P1;\n\t" \
            "WAIT_LOOP_%=:\n\t" \
            "mbarrier.try_wait.parity.acquire.cta.shared::cta.b64 P1, [%0], %1, 0x989680;\n\t" \
            "@P1 bra.uni WAIT_DONE_%=;\n\t" \
            "bra.uni WAIT_LOOP_%=;\n\t" \
            "WAIT_DONE_%=:\n\t}" :: "r"(_m), "r"(_p) : "memory"); \
    } \
} while (0)
#define TCGEN05_LD_X32(r, a) \
    asm volatile("tcgen05.ld.sync.aligned.32x32b.x32.b32 " \
        "{%0, %1, %2, %3, %4, %5, %6, %7, %8, %9, %10, %11, %12, %13, %14, %15, " \
        " %16, %17, %18, %19, %20, %21, %22, %23, %24, %25, %26, %27, %28, %29, %30, %31}, [%32];" \
        : "=r"((r)[0]),  "=r"((r)[1]),  "=r"((r)[2]),  "=r"((r)[3]), \
          "=r"((r)[4]),  "=r"((r)[5]),  "=r"((r)[6]),  "=r"((r)[7]), \
          "=r"((r)[8]),  "=r"((r)[9]),  "=r"((r)[10]), "=r"((r)[11]), \
          "=r"((r)[12]), "=r"((r)[13]), "=r"((r)[14]), "=r"((r)[15]), \
          "=r"((r)[16]), "=r"((r)[17]), "=r"((r)[18]), "=r"((r)[19]), \
          "=r"((r)[20]), "=r"((r)[21]), "=r"((r)[22]), "=r"((r)[23]), \
          "=r"((r)[24]), "=r"((r)[25]), "=r"((r)[26]), "=r"((r)[27]), \
          "=r"((r)[28]), "=r"((r)[29]), "=r"((r)[30]), "=r"((r)[31]) \
        : "r"(a))

__device__ __forceinline__ void mma_bf16_ss(uint32_t d, uint64_t a, uint64_t b, uint32_t en) {
    asm volatile(
        "{\n\t.reg .pred p;\n\tsetp.ne.u32 p, %5, 0;\n\t"
        "tcgen05.mma.cta_group::1.kind::f16 [%0], %1, %2, %3, {%4, %4, %4, %4}, p;\n\t}"
        :: "r"(d), "l"(a), "l"(b), "r"(IDESC), "r"(0u), "r"(en) : "memory");
}
__device__ __forceinline__ uint64_t make_desc(uint32_t addr) {
    const uint64_t base = (uint64_t(2) << 61) | (uint64_t(1) << 46) |
                          (uint64_t(64) << 32) | (uint64_t(1) << 16);
    return base | ((uint64_t)(addr >> 4) & 0x3FFF);
}
#endif  // USE_TC

// ---------------- fallback (FFMA2) helpers ----------------
__device__ __forceinline__ u64 pack2(float x) {
    u64 r;
    unsigned int xi = __float_as_uint(x);
    asm("mov.b64 %0, {%1, %1};" : "=l"(r) : "r"(xi));
    return r;
}
__device__ __forceinline__ void fma2(u64& d, u64 a, u64 b) {
    asm("fma.rn.f32x2 %0, %1, %2, %0;" : "+l"(d) : "l"(a), "l"(b));
}
__device__ __forceinline__ void unpack2(u64 v, float& lo, float& hi) {
    unsigned int a, b;
    asm("mov.b64 {%0, %1}, %2;" : "=r"(a), "=r"(b) : "l"(v));
    lo = __uint_as_float(a);
    hi = __uint_as_float(b);
}
__device__ __forceinline__ void load_wt(float* sm_wt, const float* __restrict__ w, int tid) {
    for (int idx = tid; idx < 128 * 32; idx += THREADS) {
        int j = idx >> 5;
        int kc = (idx & 31) << 2;
        float4 v = *(const float4*)(w + j * 128 + kc);
        sm_wt[(kc + 0) * WP + j] = v.x;
        sm_wt[(kc + 1) * WP + j] = v.y;
        sm_wt[(kc + 2) * WP + j] = v.z;
        sm_wt[(kc + 3) * WP + j] = v.w;
    }
}
// 1024-thread fallback: each thread 4 rows x 8 cols (4 f32x2 pairs)
__device__ __forceinline__ void fb_gemm(u64 (&acc)[4][4], const float* sm_act,
                                        const float* sm_wt, int m, int g) {
#pragma unroll
    for (int i = 0; i < 4; ++i)
#pragma unroll
        for (int p = 0; p < 4; ++p) acc[i][p] = 0ULL;
    const float* a0 = sm_act + (g * 4) * AP;
#pragma unroll 2
    for (int k = 0; k < 128; ++k) {
        const float* wk = sm_wt + k * WP + 2 * m;
        u64 b0 = *(const u64*)(wk);
        u64 b1 = *(const u64*)(wk + 32);
        u64 b2 = *(const u64*)(wk + 64);
        u64 b3 = *(const u64*)(wk + 96);
#pragma unroll
        for (int i = 0; i < 4; ++i) {
            u64 a2 = pack2(a0[i * AP + k]);
            fma2(acc[i][0], a2, b0);
            fma2(acc[i][1], a2, b1);
            fma2(acc[i][2], a2, b2);
            fma2(acc[i][3], a2, b3);
        }
    }
}
__device__ __forceinline__ void fb_bn_relu(u64 (&acc)[4][4], float* sm_act, float* sm_scr,
                                           float* sm_sc, float* sm_sh,
                                           const float* sm_gm, const float* sm_bt,
                                           int m, int g, int tid) {
    float* ssum = sm_scr;              // [64][128]
    float* ssq  = sm_scr + 64 * 128;   // [64][128]
    __syncthreads();
#pragma unroll
    for (int p = 0; p < 4; ++p) {
        int j0 = 2 * m + 32 * p;
        float s0 = 0.f, q0 = 0.f, s1 = 0.f, q1 = 0.f;
#pragma unroll
        for (int i = 0; i < 4; ++i) {
            float lo, hi;
            unpack2(acc[i][p], lo, hi);
            s0 += lo; q0 += lo * lo;
            s1 += hi; q1 += hi * hi;
        }
        ssum[g * 128 + j0] = s0;     ssq[g * 128 + j0] = q0;
        ssum[g * 128 + j0 + 1] = s1; ssq[g * 128 + j0 + 1] = q1;
    }
    __syncthreads();
    if (tid < 128) {
        float s = 0.f, q = 0.f;
#pragma unroll
        for (int gg = 0; gg < 64; ++gg) {
            s += ssum[gg * 128 + tid];
            q += ssq[gg * 128 + tid];
        }
        float mean = s * (1.0f / 256.0f);
        float var  = q * (1.0f / 256.0f) - mean * mean;
        float inv  = rsqrtf(var + 1e-5f);
        float sc   = sm_gm[tid] * inv;
        sm_sc[tid] = sc;
        sm_sh[tid] = sm_bt[tid] - mean * sc;
    }
    __syncthreads();
#pragma unroll
    for (int p = 0; p < 4; ++p) {
        int j0 = 2 * m + 32 * p;
        float sc0 = sm_sc[j0], sh0 = sm_sh[j0];
        float sc1 = sm_sc[j0 + 1], sh1 = sm_sh[j0 + 1];
#pragma unroll
        for (int i = 0; i < 4; ++i) {
            float lo, hi;
            unpack2(acc[i][p], lo, hi);
            float2 v;
            v.x = fmaxf(fmaf(lo, sc0, sh0), 0.0f);
            v.y = fmaxf(fmaf(hi, sc1, sh1), 0.0f);
            *(float2*)(sm_act + (g * 4 + i) * AP + j0) = v;
        }
    }
}

// ============================= the MLP kernel =============================
__global__ void __launch_bounds__(THREADS, 1)
mlp_kernel(const float* __restrict__ s, const float* __restrict__ c,
           const float* __restrict__ sw1, const float* __restrict__ sg1, const float* __restrict__ sbe1,
           const float* __restrict__ sw2, const float* __restrict__ sg2, const float* __restrict__ sbe2,
           const float* __restrict__ sw3, const float* __restrict__ sb3,
           const float* __restrict__ cw1, const float* __restrict__ cg1, const float* __restrict__ cbe1,
           const float* __restrict__ cw2, const float* __restrict__ cg2, const float* __restrict__ cbe2,
           const float* __restrict__ cw3, const float* __restrict__ cb3,
           float* __restrict__ out) {
    extern __shared__ char smc[];
    const int tid = threadIdx.x;
    const bool is_c = (blockIdx.x == 0);
    const int slice = (int)blockIdx.x - 1;

    const float *G1, *G2, *B1, *B2, *B3;
    if (is_c) { G1=cg1; G2=cg2; B1=cbe1; B2=cbe2; B3=cb3; }
    else      { G1=sg1; G2=sg2; B1=sbe1; B2=sbe2; B3=sb3; }
    const int wbase = is_c ? 3 : 0;

#if USE_TC
    // ======================= tcgen05 path =======================
    char* sm = smc;
    const uint32_t smb = smem_u32(sm);
    const int wid = tid >> 5;
    const int lane = tid & 31;

    if (wid == 0) {
        TCGEN05_ALLOC(smb + OFF_TMEM, 256);
        TCGEN05_RELINQ();
    }
    if (tid == 0) {
        MBARRIER_INIT(smb + OFF_MBAR, 1);
        MBARRIER_INIT(smb + OFF_MBAR2, 1);
    }
    __syncthreads();
    uint32_t tmem;
    asm volatile("ld.shared.b32 %0, [%1];" : "=r"(tmem) : "r"(smb + OFF_TMEM));

    // BN params in regs for the 128 combiner threads
    float gmr0 = 0.f, gmr1 = 0.f, btr0 = 0.f, btr1 = 0.f;
    if (tid < 128) {
        gmr0 = G1[tid]; btr0 = B1[tid];
        gmr1 = G2[tid]; btr1 = B2[tid];
    }

    // Stage input slice: fp32 -> bf16 hi/lo split into swizzled A tiles
    {
        const float* src = is_c ? c : (s + (size_t)slice * 128);
        size_t rstride = is_c ? (size_t)128 : (size_t)512 * 128;
#pragma unroll
        for (int it = 0; it < 4; ++it) {
            int idx = tid + it * THREADS;
            int row = idx >> 4;
            int ch = idx & 15;
            const float* p = src + (size_t)row * rstride + ch * 8;
            float4 a = *(const float4*)p;
            float4 b = *(const float4*)(p + 4);
            float f[8] = {a.x, a.y, a.z, a.w, b.x, b.y, b.z, b.w};
            uint4 H, L;
            split8f(f, H, L);
            int t = row >> 7;
            uint32_t off = swb(row & 127, ch * 8) + t * 32768;
            *(uint4*)(sm + OFF_AHI + off) = H;
            *(uint4*)(sm + OFF_ALO + off) = L;
        }
    }
    // Copy W1 image (pre-split, pre-swizzled)
    {
        const uint4* srcw = &g_wbuf[wbase][0];
        uint4* dstw = (uint4*)(sm + OFF_WHI);
#pragma unroll
        for (int it = 0; it < 4; ++it) dstw[tid + it * THREADS] = srcw[tid + it * THREADS];
    }
    FENCE_PROXY();
    __syncthreads();

    // 32-warp mapping: tile = wid>>4, colq = (wid>>2)&3, rowgrp = wid&3
    const int tile = wid >> 4;
    const int jbase = ((wid >> 2) & 3) << 5;
    const int rowgrp = wid & 3;
    const int myrow = tile * 128 + rowgrp * 32 + lane;
    const int rl = myrow & 127;

    float* scv = (float*)(sm + OFF_SC);
    float* shv = (float*)(sm + OFF_SH);
    float* pst = (float*)(sm + OFF_PST);

    uint32_t d[32];

#pragma unroll 1
    for (int layer = 0; layer < 3; ++layer) {
        // ---- MMA dispatch (warp 0, elected lane): per tile 3 passes x 8 ks ----
        if (wid == 0) {
            if (elect_one_pred()) {
                uint64_t bh = make_desc(smb + OFF_WHI);
                uint64_t bl = make_desc(smb + OFF_WLO);
#pragma unroll
                for (int T = 0; T < 2; ++T) {
                    uint64_t ah = make_desc(smb + OFF_AHI + T * 32768);
                    uint64_t al = make_desc(smb + OFF_ALO + T * 32768);
#pragma unroll
                    for (int pass = 0; pass < 3; ++pass) {
                        uint64_t ad = (pass == 2) ? al : ah;
                        uint64_t bd = (pass == 1) ? bl : bh;
#pragma unroll
                        for (int ks = 0; ks < 8; ++ks) {
                            uint32_t off = ((ks >> 2) << 10) + ((ks & 3) << 1);
                            mma_bf16_ss(tmem + T * 128, ad + off, bd + off,
                                        (pass | ks) ? 1u : 0u);
                        }
                    }
                    TCGEN05_COMMIT(smb + (T == 0 ? OFF_MBAR : OFF_MBAR2));
                }
            }
        }
        // Tile groups wait their own barrier; tile0 starts LDTM under tile1 MMA
        MBARRIER_WAIT_PARITY(smb + (tile == 0 ? OFF_MBAR : OFF_MBAR2), layer & 1);
        TCGEN05_FENCE_AFTER();

        TCGEN05_LD_X32(d, tmem + tile * 128 + jbase);

        // tile0 group prefetches next-layer W (after mbar1 = all MMAs done;
        // overlaps tile1's MMA tail + both LDTMs)
        if (tile == 0 && layer < 2) {
            MBARRIER_WAIT_PARITY(smb + OFF_MBAR2, layer & 1);
            const uint4* srcw = &g_wbuf[wbase + layer + 1][0];
            uint4* dstw = (uint4*)(sm + OFF_WHI);
#pragma unroll
            for (int it = 0; it < 8; ++it) dstw[tid + it * 512] = srcw[tid + it * 512];
        }
        TCGEN05_WAIT_LD();
        TCGEN05_FENCE_BEFORE();

        if (layer < 2) {
            // ---- per-warp column (sum, sumsq) over 32 rows via butterflies ----
            {
                // sum chain
                float s16[16];
#pragma unroll
                for (int i = 0; i < 16; ++i) {
                    float dlo = __uint_as_float(d[i]);
                    float dhi = __uint_as_float(d[16 + i]);
                    bool up = (lane & 16);
                    float dk = up ? dhi : dlo;
                    float ds = up ? dlo : dhi;
                    s16[i] = dk + __shfl_xor_sync(0xFFFFFFFFu, ds, 16);
                }
                float s8[8];
#pragma unroll
                for (int i = 0; i < 8; ++i) {
                    bool up = (lane & 8);
                    float k = up ? s16[8 + i] : s16[i];
                    float sn = up ? s16[i] : s16[8 + i];
                    s8[i] = k + __shfl_xor_sync(0xFFFFFFFFu, sn, 8);
                }
                float s4[4];
#pragma unroll
                for (int i = 0; i < 4; ++i) {
                    bool up = (lane & 4);
                    float k = up ? s8[4 + i] : s8[i];
                    float sn = up ? s8[i] : s8[4 + i];
                    s4[i] = k + __shfl_xor_sync(0xFFFFFFFFu, sn, 4);
                }
                float s2[2];
#pragma unroll
                for (int i = 0; i < 2; ++i) {
                    bool up = (lane & 2);
                    float k = up ? s4[2 + i] : s4[i];
                    float sn = up ? s4[i] : s4[2 + i];
                    s2[i] = k + __shfl_xor_sync(0xFFFFFFFFu, sn, 2);
                }
                {
                    bool up = (lane & 1);
                    float k = up ? s2[1] : s2[0];
                    float sn = up ? s2[0] : s2[1];
                    float s1 = k + __shfl_xor_sync(0xFFFFFFFFu, sn, 1);
                    pst[(tile * 4 + rowgrp) * 128 + jbase + lane] = s1;
                }
                // sumsq chain
                float q16[16];
#pragma unroll
                for (int i = 0; i < 16; ++i) {
                    float dlo = __uint_as_float(d[i]);
                    float dhi = __uint_as_float(d[16 + i]);
                    bool up = (lane & 16);
                    float dk = up ? dhi : dlo;
                    float ds = up ? dlo : dhi;
                    float rv = __shfl_xor_sync(0xFFFFFFFFu, ds, 16);
                    q16[i] = fmaf(dk, dk, rv * rv);
                }
                float q8[8];
#pragma unroll
                for (int i = 0; i < 8; ++i) {
                    bool up = (lane & 8);
                    float k = up ? q16[8 + i] : q16[i];
                    float sn = up ? q16[i] : q16[8 + i];
                    q8[i] = k + __shfl_xor_sync(0xFFFFFFFFu, sn, 8);
                }
                float q4[4];
#pragma unroll
                for (int i = 0; i < 4; ++i) {
                    bool up = (lane & 4);
                    float k = up ? q8[4 + i] : q8[i];
                    float sn = up ? q8[i] : q8[4 + i];
                    q4[i] = k + __shfl_xor_sync(0xFFFFFFFFu, sn, 4);
                }
                float q2[2];
#pragma unroll
                for (int i = 0; i < 2; ++i) {
                    bool up = (lane & 2);
                    float k = up ? q4[2 + i] : q4[i];
                    float sn = up ? q4[i] : q4[2 + i];
                    q2[i] = k + __shfl_xor_sync(0xFFFFFFFFu, sn, 2);
                }
                {
                    bool up = (lane & 1);
                    float k = up ? q2[1] : q2[0];
                    float sn = up ? q2[0] : q2[1];
                    float q1 = k + __shfl_xor_sync(0xFFFFFFFFu, sn, 1);
                    pst[1024 + (tile * 4 + rowgrp) * 128 + jbase + lane] = q1;
                }
            }
            __syncthreads();

            if (tid < 128) {
                float ss = 0.f, qq = 0.f;
#pragma unroll
                for (int k = 0; k < 8; ++k) {
                    ss += pst[k * 128 + tid];
                    qq += pst[1024 + k * 128 + tid];
                }
                float mean = ss * (1.0f / 256.0f);
                float var = qq * (1.0f / 256.0f) - mean * mean;
                float inv = rsqrtf(var + 1e-5f);
                float gm = layer ? gmr1 : gmr0;
                float bt = layer ? btr1 : btr0;
                float scl = gm * inv;
                scv[tid] = scl;
                shv[tid] = bt - mean * scl;   // linear bias cancels in BN
            }
            __syncthreads();

            // Normalize + ReLU, split to bf16 hi/lo, store next A
            {
                char* hb = sm + OFF_AHI + tile * 32768;
                char* lb = sm + OFF_ALO + tile * 32768;
#pragma unroll
                for (int c8 = 0; c8 < 4; ++c8) {
                    int j0 = jbase + c8 * 8;
                    float f[8];
#pragma unroll
                    for (int i = 0; i < 8; ++i) {
                        f[i] = fmaxf(fmaf(__uint_as_float(d[c8 * 8 + i]), scv[j0 + i], shv[j0 + i]), 0.f);
                    }
                    uint4 H, L;
                    split8f(f, H, L);
                    uint32_t off = swb(rl, j0);
                    *(uint4*)(hb + off) = H;
                    *(uint4*)(lb + off) = L;
                }
            }
            FENCE_PROXY();
            __syncthreads();
        }
    }

    // ---- layer-3 epilogue: +b3, gate, write ----
    const int q0 = jbase >> 2;
    if (is_c) {
#pragma unroll
        for (int q = 0; q < 8; ++q) {
            float4 bb = __ldg((const float4*)B3 + q0 + q);
            float4 v;
            v.x = __uint_as_float(d[4 * q + 0]) + bb.x;
            v.y = __uint_as_float(d[4 * q + 1]) + bb.y;
            v.z = __uint_as_float(d[4 * q + 2]) + bb.z;
            v.w = __uint_as_float(d[4 * q + 3]) + bb.w;
            g_c_out[myrow * 32 + q0 + q] = v;
        }
        __threadfence();
        __syncthreads();
        if (tid == 0) atomicExch(&g_flag, 1);
    } else {
        if (tid == 0) {
            while (atomicAdd(&g_flag, 0) == 0) { }
            __threadfence();
        }
        __syncthreads();
        float* op = out + ((size_t)myrow * 512 + slice) * 128 + jbase;
#pragma unroll
        for (int q = 0; q < 8; ++q) {
            float4 bb = __ldg((const float4*)B3 + q0 + q);
            float4 cv = __ldcg(&g_c_out[myrow * 32 + q0 + q]);
            float4 v;
            v.x = (__uint_as_float(d[4 * q + 0]) + bb.x) * cv.x;
            v.y = (__uint_as_float(d[4 * q + 1]) + bb.y) * cv.y;
            v.z = (__uint_as_float(d[4 * q + 2]) + bb.z) * cv.z;
            v.w = (__uint_as_float(d[4 * q + 3]) + bb.w) * cv.w;
            ((float4*)op)[q] = v;
        }
    }

    __syncthreads();
    if (tid == 0) {
        MBARRIER_INVAL(smb + OFF_MBAR);
        MBARRIER_INVAL(smb + OFF_MBAR2);
    }
    __syncthreads();
    if (wid == 0) TCGEN05_DEALLOC(tmem, 256);

#else
    // ======================= FFMA2 fallback path (1024 thr) =======================
    const float *W1, *W2, *W3;
    if (is_c) { W1=cw1; W2=cw2; W3=cw3; }
    else      { W1=sw1; W2=sw2; W3=sw3; }
    float* smf = (float*)smc;
    float* sm_act = smf;
    float* sm_wt  = smf + SM_ACT_F;
    float* sm_sc  = sm_wt + SM_WT_F;
    float* sm_sh  = sm_sc + 128;
    float* sm_gm  = sm_sh + 128;
    float* sm_bt  = sm_gm + 128;
    const int m = tid & 15;
    const int g = tid >> 4;   // 0..63

    {
        const float* src = is_c ? c : (s + (size_t)slice * 128);
        const size_t rstride = is_c ? (size_t)128 : (size_t)512 * 128;
        for (int idx = tid; idx < 256 * 32; idx += THREADS) {
            int r = idx >> 5;
            int kc = (idx & 31) << 2;
            float4 v = *(const float4*)(src + (size_t)r * rstride + kc);
            *(float4*)(sm_act + r * AP + kc) = v;
        }
    }
    load_wt(sm_wt, W1, tid);
    if (tid < 128) { sm_gm[tid] = G1[tid]; sm_bt[tid] = B1[tid]; }
    __syncthreads();

    u64 acc[4][4];
    fb_gemm(acc, sm_act, sm_wt, m, g);
    fb_bn_relu(acc, sm_act, sm_wt, sm_sc, sm_sh, sm_gm, sm_bt, m, g, tid);
    load_wt(sm_wt, W2, tid);
    if (tid < 128) { sm_gm[tid] = G2[tid]; sm_bt[tid] = B2[tid]; }
    __syncthreads();

    fb_gemm(acc, sm_act, sm_wt, m, g);
    fb_bn_relu(acc, sm_act, sm_wt, sm_sc, sm_sh, sm_gm, sm_bt, m, g, tid);
    load_wt(sm_wt, W3, tid);
    if (tid < 128) sm_bt[tid] = B3[tid];
    __syncthreads();

    fb_gemm(acc, sm_act, sm_wt, m, g);

    float* gco = (float*)g_c_out;
    if (is_c) {
#pragma unroll
        for (int p = 0; p < 4; ++p) {
            int j0 = 2 * m + 32 * p;
            float bb0 = sm_bt[j0], bb1 = sm_bt[j0 + 1];
#pragma unroll
            for (int i = 0; i < 4; ++i) {
                float lo, hi;
                unpack2(acc[i][p], lo, hi);
                float2 v; v.x = lo + bb0; v.y = hi + bb1;
                *(float2*)&gco[(g * 4 + i) * 128 + j0] = v;
            }
        }
        __threadfence();
        __syncthreads();
        if (tid == 0) atomicExch(&g_flag, 1);
    } else {
        if (tid == 0) {
            while (atomicAdd(&g_flag, 0) == 0) { }
            __threadfence();
        }
        __syncthreads();
#pragma unroll
        for (int p = 0; p < 4; ++p) {
            int j0 = 2 * m + 32 * p;
            float bb0 = sm_bt[j0], bb1 = sm_bt[j0 + 1];
#pragma unroll
            for (int i = 0; i < 4; ++i) {
                int r = g * 4 + i;
                float lo, hi;
                unpack2(acc[i][p], lo, hi);
                float2 cv = __ldcg((const float2*)&gco[r * 128 + j0]);
                float2 v;
                v.x = (lo + bb0) * cv.x;
                v.y = (hi + bb1) * cv.y;
                *(float2*)(out + ((size_t)r * 512 + slice) * 128 + j0) = v;
            }
        }
    }
#endif
}

// ---- Max-pool stage 1: grid 1024 = b(256) x seg(4, 128 slices each) ----
__global__ void __launch_bounds__(256, 8)
partial_max(const float* __restrict__ so) {
    __shared__ float4 red[8][32];
    int b = blockIdx.x >> 2;
    int seg = blockIdx.x & 3;
    int c4 = threadIdx.x & 31;
    int sub = threadIdx.x >> 5;
    const float4* p = (const float4*)(so + ((size_t)b * 512 + seg * 128 + sub * 16) * 128) + c4;
    float4 mx = make_float4(-3.4e38f, -3.4e38f, -3.4e38f, -3.4e38f);
#pragma unroll 16
    for (int i = 0; i < 16; ++i) {
        float4 v = p[(size_t)i * 32];
        mx.x = fmaxf(mx.x, v.x); mx.y = fmaxf(mx.y, v.y);
        mx.z = fmaxf(mx.z, v.z); mx.w = fmaxf(mx.w, v.w);
    }
    red[sub][c4] = mx;
    __syncthreads();
    if (threadIdx.x < 32) {
        float4 r = red[0][c4];
#pragma unroll
        for (int ss = 1; ss < 8; ++ss) {
            float4 v = red[ss][c4];
            r.x = fmaxf(r.x, v.x); r.y = fmaxf(r.y, v.y);
            r.z = fmaxf(r.z, v.z); r.w = fmaxf(r.w, v.w);
        }
        g_part[(size_t)blockIdx.x * 32 + c4] = r;
    }
}

// ---- Max-pool stage 2; also resets flag for graph replay ----
__global__ void final_max(float* __restrict__ agg) {
    if (blockIdx.x == 0 && threadIdx.x == 0) g_flag = 0;
    int idx = blockIdx.x * 256 + threadIdx.x;
    int b = idx >> 5;
    int c4 = idx & 31;
    float4 r = g_part[(size_t)(b * 4) * 32 + c4];
#pragma unroll
    for (int seg = 1; seg < 4; ++seg) {
        float4 v = g_part[(size_t)(b * 4 + seg) * 32 + c4];
        r.x = fmaxf(r.x, v.x); r.y = fmaxf(r.y, v.y);
        r.z = fmaxf(r.z, v.z); r.w = fmaxf(r.w, v.w);
    }
    ((float4*)agg)[idx] = r;
}

extern "C" void kernel_launch(void* const* d_in, const int* in_sizes, int n_in,
                              void* d_out, int out_size) {
    const float* s    = (const float*)d_in[0];
    const float* c    = (const float*)d_in[1];
    const float* sw1  = (const float*)d_in[2];
    const float* sg1  = (const float*)d_in[4];
    const float* sbe1 = (const float*)d_in[5];
    const float* sw2  = (const float*)d_in[6];
    const float* sg2  = (const float*)d_in[8];
    const float* sbe2 = (const float*)d_in[9];
    const float* sw3  = (const float*)d_in[10];
    const float* sb3  = (const float*)d_in[11];
    const float* cw1  = (const float*)d_in[12];
    const float* cg1  = (const float*)d_in[14];
    const float* cbe1 = (const float*)d_in[15];
    const float* cw2  = (const float*)d_in[16];
    const float* cg2  = (const float*)d_in[18];
    const float* cbe2 = (const float*)d_in[19];
    const float* cw3  = (const float*)d_in[20];
    const float* cb3  = (const float*)d_in[21];
    float* out = (float*)d_out;

    cudaFuncSetAttribute(mlp_kernel, cudaFuncAttributeMaxDynamicSharedMemorySize, SM_BYTES_MAX);

    presplit_w<<<6, 512>>>(sw1, sw2, sw3, cw1, cw2, cw3);

    mlp_kernel<<<513, THREADS, SM_BYTES_MAX>>>(s, c,
                                               sw1, sg1, sbe1, sw2, sg2, sbe2, sw3, sb3,
                                               cw1, cg1, cbe1, cw2, cg2, cbe2, cw3, cb3,
                                               out);

    float* agg = out + ((size_t)out_size - 256 * 128);
    partial_max<<<1024, 256>>>(out);
    final_max<<<32, 256>>>(agg);
}

// round 7
// speedup vs baseline: 4.4432x; 1.1482x over previous
#include <cuda_runtime.h>
#include <cuda_bf16.h>
#include <cstdint>

// CGBlock: per-slice 3-layer MLP (Linear->BN->ReLU x2 ->Linear), context gate,
// max-pool. B=256, S=512, D=128 fp32.
//
// R7: each slice handled by a 2-CTA cluster using cta_group::2 bf16x3-split
// MMA (M=256 across the pair; each CTA holds 128 A-rows + 64 W-cols).
// ~102KB smem/CTA -> 2 CTAs/SM -> per-slice latency ~halves.
// BN stats: warp butterflies -> smem partials -> DSMEM exchange across pair.

#define THREADS 512

#if defined(__CUDA_ARCH__) && (defined(__CUDA_ARCH_FEAT_SM103_ALL) || defined(__CUDA_ARCH_FEAT_SM100_ALL) || defined(__CUDA_ARCH_FEAT_SM101_ALL))
#define USE_TC 1
#else
#define USE_TC 0
#endif

// ---------------- shared device state ----------------
__device__ float4 g_c_out[256 * 32];
__device__ int g_flag = 0;
__device__ float4 g_part[1024 * 32];
__device__ uint4 g_wbuf2[6][2][2048];   // [matrix][rank]: 64-row W half, hi 16KB | lo 16KB

// ---------------- TC-path SMEM layout (bytes) ----------------
#define OFF_TMEM 0
#define OFF_MBAR 8
#define OFF_AHI  1024      // A_hi: 128r x 128k bf16 blocked-SW128 = 32768
#define OFF_ALO  33792     // A_lo: 32768
#define OFF_WHI  66560     // W_hi half: 64r x 128k = 16384
#define OFF_WLO  82944     // W_lo half: 16384
#define OFF_SC   99328     // BN scale f32[128]
#define OFF_SH   99840     // BN shift f32[128]
#define OFF_PST  100352    // f32[1024]: 512 sum + 512 sumsq partials
#define SM_TC_BYTES 104448

// idesc kind::f16 cg2: c=F32, a=BF16, b=BF16, N=128, M=256
#define IDESC2 0x10200490u

typedef unsigned long long u64;

__device__ __forceinline__ uint32_t smem_u32(const void* p) {
    uint32_t a;
    asm("{ .reg .u64 t; cvta.to.shared.u64 t, %1; cvt.u32.u64 %0, t; }" : "=r"(a) : "l"(p));
    return a;
}

// Blocked SW128 addr, 128-row bf16 tile (16 atom-rows x 2 atom-cols).
__device__ __forceinline__ uint32_t swb(int rl, int j0) {
    uint32_t off = (uint32_t)((((rl >> 3) + ((j0 >> 6) << 4)) << 10) + ((rl & 7) << 7) + ((j0 & 63) << 1));
    return off ^ ((off >> 3) & 0x70);
}
// Blocked SW128 addr, 64-row bf16 tile (8 atom-rows x 2 atom-cols).
__device__ __forceinline__ uint32_t swb64(int rl, int j0) {
    uint32_t off = (uint32_t)((((rl >> 3) + ((j0 >> 6) << 3)) << 10) + ((rl & 7) << 7) + ((j0 & 63) << 1));
    return off ^ ((off >> 3) & 0x70);
}

// Fast split: hi = bf16-truncate (PRMT pack), lo = rn_bf16(x - hi).
__device__ __forceinline__ void split8f(const float* f, uint4& h, uint4& l) {
    uint32_t hh[4], ll[4];
#pragma unroll
    for (int i = 0; i < 4; ++i) {
        float x = f[2 * i], y = f[2 * i + 1];
        uint32_t bx = __float_as_uint(x), by = __float_as_uint(y);
        uint32_t hp;
        asm("prmt.b32 %0, %1, %2, 0x7632;" : "=r"(hp) : "r"(bx), "r"(by));
        hh[i] = hp;
        float lx = x - __uint_as_float(bx & 0xFFFF0000u);
        float ly = y - __uint_as_float(by & 0xFFFF0000u);
        uint32_t lp;
        asm("cvt.rn.bf16x2.f32 %0, %1, %2;" : "=r"(lp) : "f"(ly), "f"(lx));
        ll[i] = lp;
    }
    h = make_uint4(hh[0], hh[1], hh[2], hh[3]);
    l = make_uint4(ll[0], ll[1], ll[2], ll[3]);
}

// ---- prologue: split 6 weight matrices into per-rank swizzled halves ----
// grid 12: bid = matrix*2 + rank; rank r holds W output-rows r*64..r*64+63.
__global__ void __launch_bounds__(256, 1)
presplit_w(const float* __restrict__ w0, const float* __restrict__ w1,
           const float* __restrict__ w2, const float* __restrict__ w3,
           const float* __restrict__ w4, const float* __restrict__ w5) {
    const float* W[6] = {w0, w1, w2, w3, w4, w5};
    int mat = blockIdx.x >> 1;
    int rank = blockIdx.x & 1;
    const float* w = W[mat] + rank * 64 * 128;
    char* dst = (char*)&g_wbuf2[mat][rank][0];
#pragma unroll
    for (int it = 0; it < 4; ++it) {
        int idx = threadIdx.x + it * 256;
        int row = idx >> 4;
        int ch = idx & 15;
        const float* p = w + row * 128 + ch * 8;
        float4 a = *(const float4*)p;
        float4 b = *(const float4*)(p + 4);
        float f[8] = {a.x, a.y, a.z, a.w, b.x, b.y, b.z, b.w};
        uint4 H, L;
        split8f(f, H, L);
        uint32_t off = swb64(row, ch * 8);
        *(uint4*)(dst + off) = H;
        *(uint4*)(dst + 16384 + off) = L;
    }
}

#if USE_TC
// ---------------- tcgen05 / cluster PTX (arch-specific passes only) ----------------
__device__ __forceinline__ uint32_t elect_one_pred() {
    uint32_t pred;
    asm volatile("{\n\t.reg .pred p;\n\telect.sync _|p, 0xFFFFFFFF;\n\tselp.b32 %0, 1, 0, p;\n\t}"
                 : "=r"(pred));
    return pred;
}
__device__ __forceinline__ uint32_t cluster_rank() {
    uint32_t r;
    asm("mov.u32 %0, %%cluster_ctarank;" : "=r"(r));
    return r;
}
#define CLUSTER_SYNC() do { \
    asm volatile("barrier.cluster.arrive.aligned;" ::: "memory"); \
    asm volatile("barrier.cluster.wait.aligned;" ::: "memory"); \
} while (0)
__device__ __forceinline__ float ld_dsmem_f32(uint32_t addr, uint32_t rank) {
    uint32_t ra;
    asm("mapa.shared::cluster.u32 %0, %1, %2;" : "=r"(ra) : "r"(addr), "r"(rank));
    float v;
    asm volatile("ld.shared::cluster.f32 %0, [%1];" : "=f"(v) : "r"(ra));
    return v;
}
#define TCGEN05_ALLOC_CG2(a, n) \
    asm volatile("tcgen05.alloc.cta_group::2.sync.aligned.shared::cta.b32 [%0], %1;" \
                 :: "r"((uint32_t)(a)), "r"((uint32_t)(n)) : "memory")
#define TCGEN05_DEALLOC_CG2(t, n) \
    asm volatile("tcgen05.dealloc.cta_group::2.sync.aligned.b32 %0, %1;" :: "r"(t), "r"((uint32_t)(n)))
#define TCGEN05_RELINQ_CG2() \
    asm volatile("tcgen05.relinquish_alloc_permit.cta_group::2.sync.aligned;")
#define TCGEN05_WAIT_LD()  asm volatile("tcgen05.wait::ld.sync.aligned;" ::: "memory")
#define TCGEN05_FENCE_BEFORE() asm volatile("tcgen05.fence::before_thread_sync;" ::: "memory")
#define TCGEN05_FENCE_AFTER()  asm volatile("tcgen05.fence::after_thread_sync;" ::: "memory")
#define FENCE_PROXY() asm volatile("fence.proxy.async.shared::cta;" ::: "memory")
#define MBARRIER_INIT(m, c) \
    asm volatile("mbarrier.init.shared.b64 [%0], %1;" :: "r"((uint32_t)(m)), "r"((uint32_t)(c)) : "memory")
#define MBARRIER_INVAL(m) \
    asm volatile("mbarrier.inval.shared.b64 [%0];" :: "r"((uint32_t)(m)) : "memory")
#define MBARRIER_WAIT_PARITY(mb, ph) do { \
    uint32_t _m = (uint32_t)(mb); uint32_t _p = (uint32_t)(ph); uint32_t _d; \
    asm volatile("{\n\t.reg .pred p;\n\t" \
        "mbarrier.try_wait.parity.acquire.cta.shared::cta.b64 p, [%1], %2;\n\t" \
        "selp.b32 %0, 1, 0, p;\n\t}" : "=r"(_d) : "r"(_m), "r"(_p) : "memory"); \
    if (!_d) { \
        asm volatile("{\n\t.reg .pred P1;\n\t" \
            "WAIT_LOOP_%=:\n\t" \
            "mbarrier.try_wait.parity.acquire.cta.shared::cta.b64 P1, [%0], %1, 0x989680;\n\t" \
            "@P1 bra.uni WAIT_DONE_%=;\n\t" \
            "bra.uni WAIT_LOOP_%=;\n\t" \
            "WAIT_DONE_%=:\n\t}" :: "r"(_m), "r"(_p) : "memory"); \
    } \
} while (0)
#define TCGEN05_LD_X32(r, a) \
    asm volatile("tcgen05.ld.sync.aligned.32x32b.x32.b32 " \
        "{%0, %1, %2, %3, %4, %5, %6, %7, %8, %9, %10, %11, %12, %13, %14, %15, " \
        " %16, %17, %18, %19, %20, %21, %22, %23, %24, %25, %26, %27, %28, %29, %30, %31}, [%32];" \
        : "=r"((r)[0]),  "=r"((r)[1]),  "=r"((r)[2]),  "=r"((r)[3]), \
          "=r"((r)[4]),  "=r"((r)[5]),  "=r"((r)[6]),  "=r"((r)[7]), \
          "=r"((r)[8]),  "=r"((r)[9]),  "=r"((r)[10]), "=r"((r)[11]), \
          "=r"((r)[12]), "=r"((r)[13]), "=r"((r)[14]), "=r"((r)[15]), \
          "=r"((r)[16]), "=r"((r)[17]), "=r"((r)[18]), "=r"((r)[19]), \
          "=r"((r)[20]), "=r"((r)[21]), "=r"((r)[22]), "=r"((r)[23]), \
          "=r"((r)[24]), "=r"((r)[25]), "=r"((r)[26]), "=r"((r)[27]), \
          "=r"((r)[28]), "=r"((r)[29]), "=r"((r)[30]), "=r"((r)[31]) \
        : "r"(a))

// cg2 bf16 SS MMA (kind::f16; 8-reg disable-output-lane = all enabled)
__device__ __forceinline__ void mma_bf16_cg2(uint32_t d, uint64_t a, uint64_t b, uint32_t en) {
    asm volatile(
        "{\n\t.reg .pred p;\n\tsetp.ne.u32 p, %5, 0;\n\t"
        "tcgen05.mma.cta_group::2.kind::f16 [%0], %1, %2, %3, "
        "{%4, %4, %4, %4, %4, %4, %4, %4}, p;\n\t}"
        :: "r"(d), "l"(a), "l"(b), "r"(IDESC2), "r"(0u), "r"(en) : "memory");
}
#define TCGEN05_COMMIT_MC2(mbar, mask) \
    asm volatile("tcgen05.commit.cta_group::2.mbarrier::arrive::one.shared::cluster.multicast::cluster.b64 [%0], %1;" \
                 :: "r"((uint32_t)(mbar)), "h"((uint16_t)(mask)) : "memory")

__device__ __forceinline__ uint64_t make_desc(uint32_t addr) {
    const uint64_t base = (uint64_t(2) << 61) | (uint64_t(1) << 46) |
                          (uint64_t(64) << 32) | (uint64_t(1) << 16);
    return base | ((uint64_t)(addr >> 4) & 0x3FFF);
}
#endif  // USE_TC

// ---------------- fallback helpers (compile-only on non-arch passes) ----------------
#if !USE_TC
#define AP 132
#define WP 130
#define SM_ACT_F (256 * AP)
#define SM_WT_F  (128 * WP)
__device__ __forceinline__ u64 pack2(float x) {
    u64 r;
    unsigned int xi = __float_as_uint(x);
    asm("mov.b64 %0, {%1, %1};" : "=l"(r) : "r"(xi));
    return r;
}
__device__ __forceinline__ void fma2(u64& d, u64 a, u64 b) {
    asm("fma.rn.f32x2 %0, %1, %2, %0;" : "+l"(d) : "l"(a), "l"(b));
}
__device__ __forceinline__ void unpack2(u64 v, float& lo, float& hi) {
    unsigned int a, b;
    asm("mov.b64 {%0, %1}, %2;" : "=r"(a), "=r"(b) : "l"(v));
    lo = __uint_as_float(a);
    hi = __uint_as_float(b);
}
__device__ __forceinline__ void load_wt(float* sm_wt, const float* __restrict__ w, int tid) {
    for (int idx = tid; idx < 128 * 32; idx += THREADS) {
        int j = idx >> 5;
        int kc = (idx & 31) << 2;
        float4 v = *(const float4*)(w + j * 128 + kc);
        sm_wt[(kc + 0) * WP + j] = v.x;
        sm_wt[(kc + 1) * WP + j] = v.y;
        sm_wt[(kc + 2) * WP + j] = v.z;
        sm_wt[(kc + 3) * WP + j] = v.w;
    }
}
__device__ __forceinline__ void fb_gemm(u64 (&acc)[8][4], const float* sm_act,
                                        const float* sm_wt, int m, int g) {
#pragma unroll
    for (int i = 0; i < 8; ++i)
#pragma unroll
        for (int p = 0; p < 4; ++p) acc[i][p] = 0ULL;
    const float* a0 = sm_act + (g * 8) * AP;
#pragma unroll 2
    for (int k = 0; k < 128; ++k) {
        const float* wk = sm_wt + k * WP + 2 * m;
        u64 b0 = *(const u64*)(wk);
        u64 b1 = *(const u64*)(wk + 32);
        u64 b2 = *(const u64*)(wk + 64);
        u64 b3 = *(const u64*)(wk + 96);
#pragma unroll
        for (int i = 0; i < 8; ++i) {
            u64 a2 = pack2(a0[i * AP + k]);
            fma2(acc[i][0], a2, b0);
            fma2(acc[i][1], a2, b1);
            fma2(acc[i][2], a2, b2);
            fma2(acc[i][3], a2, b3);
        }
    }
}
__device__ __forceinline__ void fb_bn_relu(u64 (&acc)[8][4], float* sm_act, float* sm_scr,
                                           float* sm_sc, float* sm_sh,
                                           const float* sm_gm, const float* sm_bt,
                                           int m, int g, int tid) {
    float* ssum = sm_scr;
    float* ssq  = sm_scr + 32 * 128;
    __syncthreads();
#pragma unroll
    for (int p = 0; p < 4; ++p) {
        int j0 = 2 * m + 32 * p;
        float s0 = 0.f, q0 = 0.f, s1 = 0.f, q1 = 0.f;
#pragma unroll
        for (int i = 0; i < 8; ++i) {
            float lo, hi;
            unpack2(acc[i][p], lo, hi);
            s0 += lo; q0 += lo * lo;
            s1 += hi; q1 += hi * hi;
        }
        ssum[g * 128 + j0] = s0;     ssq[g * 128 + j0] = q0;
        ssum[g * 128 + j0 + 1] = s1; ssq[g * 128 + j0 + 1] = q1;
    }
    __syncthreads();
    if (tid < 128) {
        float s = 0.f, q = 0.f;
#pragma unroll
        for (int gg = 0; gg < 32; ++gg) {
            s += ssum[gg * 128 + tid];
            q += ssq[gg * 128 + tid];
        }
        float mean = s * (1.0f / 256.0f);
        float var  = q * (1.0f / 256.0f) - mean * mean;
        float inv  = rsqrtf(var + 1e-5f);
        float sc   = sm_gm[tid] * inv;
        sm_sc[tid] = sc;
        sm_sh[tid] = sm_bt[tid] - mean * sc;
    }
    __syncthreads();
#pragma unroll
    for (int p = 0; p < 4; ++p) {
        int j0 = 2 * m + 32 * p;
        float sc0 = sm_sc[j0], sh0 = sm_sh[j0];
        float sc1 = sm_sc[j0 + 1], sh1 = sm_sh[j0 + 1];
#pragma unroll
        for (int i = 0; i < 8; ++i) {
            float lo, hi;
            unpack2(acc[i][p], lo, hi);
            float2 v;
            v.x = fmaxf(fmaf(lo, sc0, sh0), 0.0f);
            v.y = fmaxf(fmaf(hi, sc1, sh1), 0.0f);
            *(float2*)(sm_act + (g * 8 + i) * AP + j0) = v;
        }
    }
}
#endif  // !USE_TC

// ============================= the MLP kernel =============================
__global__ void __launch_bounds__(THREADS, 2) __cluster_dims__(2, 1, 1)
mlp_kernel(const float* __restrict__ s, const float* __restrict__ c,
           const float* __restrict__ sw1, const float* __restrict__ sg1, const float* __restrict__ sbe1,
           const float* __restrict__ sw2, const float* __restrict__ sg2, const float* __restrict__ sbe2,
           const float* __restrict__ sw3, const float* __restrict__ sb3,
           const float* __restrict__ cw1, const float* __restrict__ cg1, const float* __restrict__ cbe1,
           const float* __restrict__ cw2, const float* __restrict__ cg2, const float* __restrict__ cbe2,
           const float* __restrict__ cw3, const float* __restrict__ cb3,
           float* __restrict__ out) {
    extern __shared__ char smc[];
    const int tid = threadIdx.x;
    const bool is_c = ((blockIdx.x >> 1) == 0);
    const int slice = (int)(blockIdx.x >> 1) - 1;

    const float *G1, *G2, *B1, *B2, *B3;
    if (is_c) { G1=cg1; G2=cg2; B1=cbe1; B2=cbe2; B3=cb3; }
    else      { G1=sg1; G2=sg2; B1=sbe1; B2=sbe2; B3=sb3; }
    const int wbase = is_c ? 3 : 0;

#if USE_TC
    // ======================= cg2 tcgen05 path =======================
    char* sm = smc;
    const uint32_t smb = smem_u32(sm);
    const int wid = tid >> 5;
    const int lane = tid & 31;
    const uint32_t rank = cluster_rank();
    const uint32_t peer = rank ^ 1u;

    if (wid == 0) {
        TCGEN05_ALLOC_CG2(smb + OFF_TMEM, 128);
        TCGEN05_RELINQ_CG2();
    }
    if (tid == 0) MBARRIER_INIT(smb + OFF_MBAR, 1);
    __syncthreads();
    uint32_t tmem;
    asm volatile("ld.shared.b32 %0, [%1];" : "=r"(tmem) : "r"(smb + OFF_TMEM));

    // Stage my 128 A-rows (global batch rows rank*128..): fp32 -> bf16 hi/lo
    {
#pragma unroll
        for (int it = 0; it < 4; ++it) {
            int idx = tid + it * THREADS;
            int row = idx >> 4;                 // 0..127 local
            int ch = idx & 15;
            int grow = (int)rank * 128 + row;   // global batch row
            const float* p = is_c ? (c + (size_t)grow * 128 + ch * 8)
                                  : (s + ((size_t)grow * 512 + slice) * 128 + ch * 8);
            float4 a = *(const float4*)p;
            float4 b = *(const float4*)(p + 4);
            float f[8] = {a.x, a.y, a.z, a.w, b.x, b.y, b.z, b.w};
            uint4 H, L;
            split8f(f, H, L);
            uint32_t off = swb(row, ch * 8);
            *(uint4*)(sm + OFF_AHI + off) = H;
            *(uint4*)(sm + OFF_ALO + off) = L;
        }
    }
    // Copy my W1 half (pre-split, pre-swizzled): 32KB
    {
        const uint4* srcw = &g_wbuf2[wbase][rank][0];
        uint4* dstw = (uint4*)(sm + OFF_WHI);
#pragma unroll
        for (int it = 0; it < 4; ++it) dstw[tid + it * THREADS] = srcw[tid + it * THREADS];
    }
    FENCE_PROXY();

    // warp mapping: rowgrp = wid&3 (TMEM subpartition), colgrp = wid>>2 (32 cols)
    const int rowgrp = wid & 3;
    const int colgrp = wid >> 2;
    const int lrow = rowgrp * 32 + lane;        // local row 0..127
    const int jbase = colgrp * 32;

    float* scv = (float*)(sm + OFF_SC);
    float* shv = (float*)(sm + OFF_SH);
    float* pst = (float*)(sm + OFF_PST);
    const uint32_t pst_addr = smb + OFF_PST;

    uint32_t d[32];

#pragma unroll 1
    for (int layer = 0; layer < 3; ++layer) {
        // both CTAs' A/W ready (and, layer 0, mbar init) before MMA touches peer smem
        CLUSTER_SYNC();

        if (rank == 0 && wid == 0) {
            if (elect_one_pred()) {
                uint64_t ah = make_desc(smb + OFF_AHI);
                uint64_t al = make_desc(smb + OFF_ALO);
                uint64_t bh = make_desc(smb + OFF_WHI);
                uint64_t bl = make_desc(smb + OFF_WLO);
#pragma unroll
                for (int pass = 0; pass < 3; ++pass) {
                    uint64_t ad = (pass == 2) ? al : ah;
                    uint64_t bd = (pass == 1) ? bl : bh;
#pragma unroll
                    for (int ks = 0; ks < 8; ++ks) {
                        uint32_t aoff = ((ks >> 2) << 10) + ((ks & 3) << 1);
                        uint32_t boff = ((ks >> 2) << 9) + ((ks & 3) << 1);
                        mma_bf16_cg2(tmem, ad + aoff, bd + boff, (pass | ks) ? 1u : 0u);
                    }
                }
                TCGEN05_COMMIT_MC2(smb + OFF_MBAR, 0x3);
            }
        }
        MBARRIER_WAIT_PARITY(smb + OFF_MBAR, layer & 1);
        TCGEN05_FENCE_AFTER();

        TCGEN05_LD_X32(d, tmem + jbase);

        // prefetch next-layer W half (MMA chain fully done -> W region free)
        if (layer < 2) {
            const uint4* srcw = &g_wbuf2[wbase + layer + 1][rank][0];
            uint4* dstw = (uint4*)(sm + OFF_WHI);
#pragma unroll
            for (int it = 0; it < 4; ++it) dstw[tid + it * THREADS] = srcw[tid + it * THREADS];
        }
        TCGEN05_WAIT_LD();
        TCGEN05_FENCE_BEFORE();

        if (layer < 2) {
            // ---- per-warp (sum, sumsq) over 32 rows via butterfly transpose ----
            {
                float s16[16];
#pragma unroll
                for (int i = 0; i < 16; ++i) {
                    float dlo = __uint_as_float(d[i]);
                    float dhi = __uint_as_float(d[16 + i]);
                    bool up = (lane & 16);
                    float dk = up ? dhi : dlo;
                    float ds = up ? dlo : dhi;
                    s16[i] = dk + __shfl_xor_sync(0xFFFFFFFFu, ds, 16);
                }
                float s8[8];
#pragma unroll
                for (int i = 0; i < 8; ++i) {
                    bool up = (lane & 8);
                    float k = up ? s16[8 + i] : s16[i];
                    float sn = up ? s16[i] : s16[8 + i];
                    s8[i] = k + __shfl_xor_sync(0xFFFFFFFFu, sn, 8);
                }
                float s4[4];
#pragma unroll
                for (int i = 0; i < 4; ++i) {
                    bool up = (lane & 4);
                    float k = up ? s8[4 + i] : s8[i];
                    float sn = up ? s8[i] : s8[4 + i];
                    s4[i] = k + __shfl_xor_sync(0xFFFFFFFFu, sn, 4);
                }
                float s2[2];
#pragma unroll
                for (int i = 0; i < 2; ++i) {
                    bool up = (lane & 2);
                    float k = up ? s4[2 + i] : s4[i];
                    float sn = up ? s4[i] : s4[2 + i];
                    s2[i] = k + __shfl_xor_sync(0xFFFFFFFFu, sn, 2);
                }
                {
                    bool up = (lane & 1);
                    float k = up ? s2[1] : s2[0];
                    float sn = up ? s2[0] : s2[1];
                    float s1 = k + __shfl_xor_sync(0xFFFFFFFFu, sn, 1);
                    pst[rowgrp * 128 + jbase + lane] = s1;
                }
                float q16[16];
#pragma unroll
                for (int i = 0; i < 16; ++i) {
                    float dlo = __uint_as_float(d[i]);
                    float dhi = __uint_as_float(d[16 + i]);
                    bool up = (lane & 16);
                    float dk = up ? dhi : dlo;
                    float ds = up ? dlo : dhi;
                    float rv = __shfl_xor_sync(0xFFFFFFFFu, ds, 16);
                    q16[i] = fmaf(dk, dk, rv * rv);
                }
                float q8[8];
#pragma unroll
                for (int i = 0; i < 8; ++i) {
                    bool up = (lane & 8);
                    float k = up ? q16[8 + i] : q16[i];
                    float sn = up ? q16[i] : q16[8 + i];
                    q8[i] = k + __shfl_xor_sync(0xFFFFFFFFu, sn, 8);
                }
                float q4[4];
#pragma unroll
                for (int i = 0; i < 4; ++i) {
                    bool up = (lane & 4);
                    float k = up ? q8[4 + i] : q8[i];
                    float sn = up ? q8[i] : q8[4 + i];
                    q4[i] = k + __shfl_xor_sync(0xFFFFFFFFu, sn, 4);
                }
                float q2[2];
#pragma unroll
                for (int i = 0; i < 2; ++i) {
                    bool up = (lane & 2);
                    float k = up ? q4[2 + i] : q4[i];
                    float sn = up ? q4[i] : q4[2 + i];
                    q2[i] = k + __shfl_xor_sync(0xFFFFFFFFu, sn, 2);
                }
                {
                    bool up = (lane & 1);
                    float k = up ? q2[1] : q2[0];
                    float sn = up ? q2[0] : q2[1];
                    float q1 = k + __shfl_xor_sync(0xFFFFFFFFu, sn, 1);
                    pst[512 + rowgrp * 128 + jbase + lane] = q1;
                }
            }
            // both CTAs' partials visible cluster-wide
            CLUSTER_SYNC();

            if (tid < 128) {
                float ss = pst[tid] + pst[128 + tid] + pst[256 + tid] + pst[384 + tid];
                float qq = pst[512 + tid] + pst[640 + tid] + pst[768 + tid] + pst[896 + tid];
#pragma unroll
                for (int k = 0; k < 4; ++k) {
                    ss += ld_dsmem_f32(pst_addr + (uint32_t)(k * 128 + tid) * 4u, peer);
                    qq += ld_dsmem_f32(pst_addr + (uint32_t)(512 + k * 128 + tid) * 4u, peer);
                }
                float mean = ss * (1.0f / 256.0f);
                float var = qq * (1.0f / 256.0f) - mean * mean;
                float inv = rsqrtf(var + 1e-5f);
                float gm = __ldg((layer ? G2 : G1) + tid);
                float bt = __ldg((layer ? B2 : B1) + tid);
                float scl = gm * inv;
                scv[tid] = scl;
                shv[tid] = bt - mean * scl;   // linear bias cancels in BN
            }
            __syncthreads();

            // normalize + ReLU, split to bf16 hi/lo, store next A (own half)
            {
#pragma unroll
                for (int c8 = 0; c8 < 4; ++c8) {
                    int j0 = jbase + c8 * 8;
                    float f[8];
#pragma unroll
                    for (int i = 0; i < 8; ++i) {
                        f[i] = fmaxf(fmaf(__uint_as_float(d[c8 * 8 + i]), scv[j0 + i], shv[j0 + i]), 0.f);
                    }
                    uint4 H, L;
                    split8f(f, H, L);
                    uint32_t off = swb(lrow, j0);
                    *(uint4*)(sm + OFF_AHI + off) = H;
                    *(uint4*)(sm + OFF_ALO + off) = L;
                }
            }
            FENCE_PROXY();
            // next iteration's CLUSTER_SYNC orders A'/W for the next MMA
        }
    }

    // ---- layer-3 epilogue: +b3, gate, write ----
    const int grow = (int)rank * 128 + lrow;     // global batch row
    const int q0 = jbase >> 2;
    if (is_c) {
#pragma unroll
        for (int q = 0; q < 8; ++q) {
            float4 bb = __ldg((const float4*)B3 + q0 + q);
            float4 v;
            v.x = __uint_as_float(d[4 * q + 0]) + bb.x;
            v.y = __uint_as_float(d[4 * q + 1]) + bb.y;
            v.z = __uint_as_float(d[4 * q + 2]) + bb.z;
            v.w = __uint_as_float(d[4 * q + 3]) + bb.w;
            g_c_out[grow * 32 + q0 + q] = v;
        }
        __threadfence();
        CLUSTER_SYNC();   // both c-CTAs' writes done
        if (rank == 0 && tid == 0) atomicExch(&g_flag, 1);
    } else {
        if (tid == 0) {
            while (atomicAdd(&g_flag, 0) == 0) { }
            __threadfence();
        }
        __syncthreads();
        float* op = out + ((size_t)grow * 512 + slice) * 128 + jbase;
#pragma unroll
        for (int q = 0; q < 8; ++q) {
            float4 bb = __ldg((const float4*)B3 + q0 + q);
            float4 cv = __ldcg(&g_c_out[grow * 32 + q0 + q]);
            float4 v;
            v.x = (__uint_as_float(d[4 * q + 0]) + bb.x) * cv.x;
            v.y = (__uint_as_float(d[4 * q + 1]) + bb.y) * cv.y;
            v.z = (__uint_as_float(d[4 * q + 2]) + bb.z) * cv.z;
            v.w = (__uint_as_float(d[4 * q + 3]) + bb.w) * cv.w;
            ((float4*)op)[q] = v;
        }
    }

    CLUSTER_SYNC();
    if (tid == 0) MBARRIER_INVAL(smb + OFF_MBAR);
    __syncthreads();
    if (wid == 0) TCGEN05_DEALLOC_CG2(tmem, 128);

#else
    // ============== FFMA2 fallback (compile-only; sm_103a SASS always runs) ==============
    if (blockIdx.x & 1) return;   // rank 1 idles in fallback
    const float *W1, *W2, *W3;
    if (is_c) { W1=cw1; W2=cw2; W3=cw3; }
    else      { W1=sw1; W2=sw2; W3=sw3; }
    float* smf = (float*)smc;
    float* sm_act = smf;
    float* sm_wt  = smf + SM_ACT_F;
    float* sm_sc  = sm_wt + SM_WT_F;
    float* sm_sh  = sm_sc + 128;
    float* sm_gm  = sm_sh + 128;
    float* sm_bt  = sm_gm + 128;
    const int m = tid & 15;
    const int g = tid >> 4;

    {
        const float* src = is_c ? c : (s + (size_t)slice * 128);
        const size_t rstride = is_c ? (size_t)128 : (size_t)512 * 128;
        for (int idx = tid; idx < 256 * 32; idx += THREADS) {
            int r = idx >> 5;
            int kc = (idx & 31) << 2;
            float4 v = *(const float4*)(src + (size_t)r * rstride + kc);
            *(float4*)(sm_act + r * AP + kc) = v;
        }
    }
    load_wt(sm_wt, W1, tid);
    if (tid < 128) { sm_gm[tid] = G1[tid]; sm_bt[tid] = B1[tid]; }
    __syncthreads();

    u64 acc[8][4];
    fb_gemm(acc, sm_act, sm_wt, m, g);
    fb_bn_relu(acc, sm_act, sm_wt, sm_sc, sm_sh, sm_gm, sm_bt, m, g, tid);
    load_wt(sm_wt, W2, tid);
    if (tid < 128) { sm_gm[tid] = G2[tid]; sm_bt[tid] = B2[tid]; }
    __syncthreads();

    fb_gemm(acc, sm_act, sm_wt, m, g);
    fb_bn_relu(acc, sm_act, sm_wt, sm_sc, sm_sh, sm_gm, sm_bt, m, g, tid);
    load_wt(sm_wt, W3, tid);
    if (tid < 128) sm_bt[tid] = B3[tid];
    __syncthreads();

    fb_gemm(acc, sm_act, sm_wt, m, g);

    float* gco = (float*)g_c_out;
    if (is_c) {
#pragma unroll
        for (int p = 0; p < 4; ++p) {
            int j0 = 2 * m + 32 * p;
            float bb0 = sm_bt[j0], bb1 = sm_bt[j0 + 1];
#pragma unroll
            for (int i = 0; i < 8; ++i) {
                float lo, hi;
                unpack2(acc[i][p], lo, hi);
                float2 v; v.x = lo + bb0; v.y = hi + bb1;
                *(float2*)&gco[(g * 8 + i) * 128 + j0] = v;
            }
        }
        __threadfence();
        __syncthreads();
        if (tid == 0) atomicExch(&g_flag, 1);
    } else {
        if (tid == 0) {
            while (atomicAdd(&g_flag, 0) == 0) { }
            __threadfence();
        }
        __syncthreads();
#pragma unroll
        for (int p = 0; p < 4; ++p) {
            int j0 = 2 * m + 32 * p;
            float bb0 = sm_bt[j0], bb1 = sm_bt[j0 + 1];
#pragma unroll
            for (int i = 0; i < 8; ++i) {
                int r = g * 8 + i;
                float lo, hi;
                unpack2(acc[i][p], lo, hi);
                float2 cv = __ldcg((const float2*)&gco[r * 128 + j0]);
                float2 v;
                v.x = (lo + bb0) * cv.x;
                v.y = (hi + bb1) * cv.y;
                *(float2*)(out + ((size_t)r * 512 + slice) * 128 + j0) = v;
            }
        }
    }
#endif
}

// ---- Max-pool stage 1: grid 1024 = b(256) x seg(4, 128 slices each) ----
__global__ void __launch_bounds__(256, 8)
partial_max(const float* __restrict__ so) {
    __shared__ float4 red[8][32];
    int b = blockIdx.x >> 2;
    int seg = blockIdx.x & 3;
    int c4 = threadIdx.x & 31;
    int sub = threadIdx.x >> 5;
    const float4* p = (const float4*)(so + ((size_t)b * 512 + seg * 128 + sub * 16) * 128) + c4;
    float4 mx = make_float4(-3.4e38f, -3.4e38f, -3.4e38f, -3.4e38f);
#pragma unroll 16
    for (int i = 0; i < 16; ++i) {
        float4 v = p[(size_t)i * 32];
        mx.x = fmaxf(mx.x, v.x); mx.y = fmaxf(mx.y, v.y);
        mx.z = fmaxf(mx.z, v.z); mx.w = fmaxf(mx.w, v.w);
    }
    red[sub][c4] = mx;
    __syncthreads();
    if (threadIdx.x < 32) {
        float4 r = red[0][c4];
#pragma unroll
        for (int ss = 1; ss < 8; ++ss) {
            float4 v = red[ss][c4];
            r.x = fmaxf(r.x, v.x); r.y = fmaxf(r.y, v.y);
            r.z = fmaxf(r.z, v.z); r.w = fmaxf(r.w, v.w);
        }
        g_part[(size_t)blockIdx.x * 32 + c4] = r;
    }
}

// ---- Max-pool stage 2; also resets flag for graph replay ----
__global__ void final_max(float* __restrict__ agg) {
    if (blockIdx.x == 0 && threadIdx.x == 0) g_flag = 0;
    int idx = blockIdx.x * 256 + threadIdx.x;
    int b = idx >> 5;
    int c4 = idx & 31;
    float4 r = g_part[(size_t)(b * 4) * 32 + c4];
#pragma unroll
    for (int seg = 1; seg < 4; ++seg) {
        float4 v = g_part[(size_t)(b * 4 + seg) * 32 + c4];
        r.x = fmaxf(r.x, v.x); r.y = fmaxf(r.y, v.y);
        r.z = fmaxf(r.z, v.z); r.w = fmaxf(r.w, v.w);
    }
    ((float4*)agg)[idx] = r;
}

extern "C" void kernel_launch(void* const* d_in, const int* in_sizes, int n_in,
                              void* d_out, int out_size) {
    const float* s    = (const float*)d_in[0];
    const float* c    = (const float*)d_in[1];
    const float* sw1  = (const float*)d_in[2];
    const float* sg1  = (const float*)d_in[4];
    const float* sbe1 = (const float*)d_in[5];
    const float* sw2  = (const float*)d_in[6];
    const float* sg2  = (const float*)d_in[8];
    const float* sbe2 = (const float*)d_in[9];
    const float* sw3  = (const float*)d_in[10];
    const float* sb3  = (const float*)d_in[11];
    const float* cw1  = (const float*)d_in[12];
    const float* cg1  = (const float*)d_in[14];
    const float* cbe1 = (const float*)d_in[15];
    const float* cw2  = (const float*)d_in[16];
    const float* cg2  = (const float*)d_in[18];
    const float* cbe2 = (const float*)d_in[19];
    const float* cw3  = (const float*)d_in[20];
    const float* cb3  = (const float*)d_in[21];
    float* out = (float*)d_out;

    cudaFuncSetAttribute(mlp_kernel, cudaFuncAttributeMaxDynamicSharedMemorySize, SM_TC_BYTES);

    presplit_w<<<12, 256>>>(sw1, sw2, sw3, cw1, cw2, cw3);

    // 513 clusters x 2 CTAs: cluster 0 = c-path, clusters 1..512 = slices
    mlp_kernel<<<1026, THREADS, SM_TC_BYTES>>>(s, c,
                                               sw1, sg1, sbe1, sw2, sg2, sbe2, sw3, sb3,
                                               cw1, cg1, cbe1, cw2, cg2, cbe2, cw3, cb3,
                                               out);

    float* agg = out + ((size_t)out_size - 256 * 128);
    partial_max<<<1024, 256>>>(out);
    final_max<<<32, 256>>>(agg);
}